// round 8
// baseline (speedup 1.0000x reference)
#include <cuda_runtime.h>
#include <cuda_bf16.h>
#include <cstdint>

#define PP 8
#define NN 1024
#define DD 768
#define HH 12
#define HSZ 64
#define SCLOG2 11.5423594967f   // 8 * log2(e)

// ---- scratch (static) ----
__device__ float gMV[PP*HH*HSZ];
__device__ __nv_bfloat16 gXhi[PP*NN*DD];
__device__ __nv_bfloat16 gXlo[PP*NN*DD];
__device__ __nv_bfloat16 gWqh[3*DD*DD];
__device__ __nv_bfloat16 gWql[3*DD*DD];
__device__ __nv_bfloat16 gWph[DD*DD];
__device__ __nv_bfloat16 gWpl[DD*DD];
__device__ __nv_bfloat16 gCh[PP*NN*DD];
__device__ __nv_bfloat16 gCl[PP*NN*DD];
// attention operands, bf16 hi/lo. Q,K: [ph][n][hs]; V transposed: [ph][hs][n]
__device__ __nv_bfloat16 gQh[PP*HH*NN*HSZ];
__device__ __nv_bfloat16 gQl[PP*HH*NN*HSZ];
__device__ __nv_bfloat16 gKh[PP*HH*NN*HSZ];
__device__ __nv_bfloat16 gKl[PP*HH*NN*HSZ];
__device__ __nv_bfloat16 gVth[PP*HH*NN*HSZ];
__device__ __nv_bfloat16 gVtl[PP*HH*NN*HSZ];

// ================= helpers =================
__device__ __forceinline__ uint32_t smem_u32(const void* p) {
    uint32_t a;
    asm("{ .reg .u64 t; cvta.to.shared.u64 t, %1; cvt.u32.u64 %0, t; }" : "=r"(a) : "l"(p));
    return a;
}
// warp-wide ldmatrix x4: threads 0-7 -> rows of m0, 8-15 -> m1, 16-23 -> m2, 24-31 -> m3
__device__ __forceinline__ void ldsm4(uint32_t& r0, uint32_t& r1, uint32_t& r2, uint32_t& r3,
                                      uint32_t addr) {
    asm volatile("ldmatrix.sync.aligned.m8n8.x4.shared.b16 {%0,%1,%2,%3}, [%4];"
                 : "=r"(r0), "=r"(r1), "=r"(r2), "=r"(r3) : "r"(addr));
}
#define CP16(saddr, gptr) \
    asm volatile("cp.async.cg.shared.global [%0], [%1], 16;" :: "r"(saddr), "l"(gptr))
#define CP_COMMIT() asm volatile("cp.async.commit_group;" ::: "memory")
#define CP_WAIT1()  asm volatile("cp.async.wait_group 1;" ::: "memory")
#define CP_WAIT0()  asm volatile("cp.async.wait_group 0;" ::: "memory")

__device__ __forceinline__ void mma16816(float* c, const uint32_t* a, const uint32_t* b) {
    asm volatile("mma.sync.aligned.m16n8k16.row.col.f32.bf16.bf16.f32 "
                 "{%0,%1,%2,%3}, {%4,%5,%6,%7}, {%8,%9}, {%0,%1,%2,%3};"
                 : "+f"(c[0]), "+f"(c[1]), "+f"(c[2]), "+f"(c[3])
                 : "r"(a[0]), "r"(a[1]), "r"(a[2]), "r"(a[3]), "r"(b[0]), "r"(b[1]));
}
// pack two floats -> bf16x2 (v0 in low half)
__device__ __forceinline__ uint32_t pack2(float v0, float v1) {
    uint32_t r;
    asm("cvt.rn.bf16x2.f32 %0, %1, %2;" : "=r"(r) : "f"(v1), "f"(v0));
    return r;
}
// hi/lo split of a float pair into two bf16x2 words
__device__ __forceinline__ void split2(float v0, float v1, uint32_t& phi, uint32_t& plo) {
    phi = pack2(v0, v1);
    float h0 = __uint_as_float(phi << 16);
    float h1 = __uint_as_float(phi & 0xffff0000u);
    plo = pack2(v0 - h0, v1 - h1);
}

// ================= split / transpose-split =================
__global__ void split_kernel(const float* __restrict__ src,
                             __nv_bfloat16* __restrict__ hi,
                             __nv_bfloat16* __restrict__ lo, int n4) {
    int i = blockIdx.x * blockDim.x + threadIdx.x;
    if (i >= n4) return;
    float4 v = ((const float4*)src)[i];
    uint32_t h[2], l[2];
    split2(v.x, v.y, h[0], l[0]);
    split2(v.z, v.w, h[1], l[1]);
    ((uint2*)hi)[i] = make_uint2(h[0], h[1]);
    ((uint2*)lo)[i] = make_uint2(l[0], l[1]);
}

__global__ void tsplit_kernel(const float* __restrict__ W,
                              __nv_bfloat16* __restrict__ Th,
                              __nv_bfloat16* __restrict__ Tl, int K, int N) {
    __shared__ float t[32][33];
    int k0 = blockIdx.y * 32, n0 = blockIdx.x * 32;
    int tx = threadIdx.x, ty = threadIdx.y;
    #pragma unroll
    for (int i = 0; i < 4; i++)
        t[ty + 8*i][tx] = W[(size_t)(k0 + ty + 8*i) * N + n0 + tx];
    __syncthreads();
    #pragma unroll
    for (int i = 0; i < 4; i++) {
        float x = t[tx][ty + 8*i];
        __nv_bfloat16 h = __float2bfloat16_rn(x);
        __nv_bfloat16 l = __float2bfloat16_rn(x - __bfloat162float(h));
        size_t o = (size_t)(n0 + ty + 8*i) * K + k0 + tx;
        Th[o] = h; Tl[o] = l;
    }
}

// ================= bf16x3 GEMM via mma.sync + ldmatrix =================
// CTA tile 128(m) x 256(n), 512 threads (16 warps = 4m x 4n, warp tile 32x64),
// K-chunk 64, double-buffered cp.async.
#define PADK 72
#define TILE_AE (128*PADK)
#define TILE_BE (256*PADK)
#define ABUF ((2*TILE_AE + 2*TILE_BE)*2)   // 110592 B per buffer
#define GEMM_SMEM (2*ABUF)                 // 221184 B

__global__ __launch_bounds__(512, 1) void gemm_mma(int mode,
                                                   const float* __restrict__ bias,
                                                   float* __restrict__ out) {
    extern __shared__ __align__(16) char smem[];
    uint32_t sb = smem_u32(smem);
    int tid = threadIdx.x, wid = tid >> 5, lane = tid & 31;
    int wm = wid & 3, wn = wid >> 2;
    int row0 = blockIdx.y * 128, col0 = blockIdx.x * 256;
    int gid = lane >> 2, tig = lane & 3;
    int lrow = lane & 15, lcol8 = (lane >> 4) << 3;   // ldmatrix address split

    const __nv_bfloat16* Ah = mode ? gCh : gXhi;
    const __nv_bfloat16* Al = mode ? gCl : gXlo;
    const __nv_bfloat16* Bh = mode ? gWph : gWqh;
    const __nv_bfloat16* Bl = mode ? gWpl : gWql;

    float acc[2][8][4];
    #pragma unroll
    for (int i = 0; i < 2; i++)
        #pragma unroll
        for (int j = 0; j < 8; j++)
            #pragma unroll
            for (int q = 0; q < 4; q++) acc[i][j][q] = 0.f;

    auto fill = [&](int s, int c) {
        int k0 = c * 64;
        uint32_t sbase = sb + s * ABUF;
        #pragma unroll
        for (int j = 0; j < 2; j++) {
            int e = j * 512 + tid;
            int r = e >> 3, v = e & 7;
            uint32_t d = sbase + (uint32_t)(r * PADK + v * 8) * 2;
            size_t go = (size_t)(row0 + r) * DD + k0 + v * 8;
            CP16(d, Ah + go);
            CP16(d + TILE_AE*2, Al + go);
        }
        #pragma unroll
        for (int j = 0; j < 4; j++) {
            int e = j * 512 + tid;
            int r = e >> 3, v = e & 7;
            uint32_t d = sbase + 2*TILE_AE*2 + (uint32_t)(r * PADK + v * 8) * 2;
            size_t go = (size_t)(col0 + r) * DD + k0 + v * 8;
            CP16(d, Bh + go);
            CP16(d + TILE_BE*2, Bl + go);
        }
        CP_COMMIT();
    };

    fill(0, 0);
    for (int c = 0; c < 12; c++) {
        if (c < 11) fill((c + 1) & 1, c + 1);
        if (c < 11) CP_WAIT1(); else CP_WAIT0();
        __syncthreads();

        uint32_t base = sb + (c & 1) * ABUF;
        uint32_t Ahb = base, Alb = base + TILE_AE*2;
        uint32_t Bhb = base + 2*TILE_AE*2, Blb = Bhb + TILE_BE*2;

        #pragma unroll
        for (int ks = 0; ks < 4; ks++) {
            int kbase = ks * 16 + lcol8;
            uint32_t ah[2][4], al[2][4];
            #pragma unroll
            for (int mt = 0; mt < 2; mt++) {
                uint32_t ao = (uint32_t)((wm*32 + mt*16 + lrow) * PADK + kbase) * 2;
                ldsm4(ah[mt][0], ah[mt][1], ah[mt][2], ah[mt][3], Ahb + ao);
                ldsm4(al[mt][0], al[mt][1], al[mt][2], al[mt][3], Alb + ao);
            }
            #pragma unroll
            for (int half = 0; half < 2; half++) {
                uint32_t bh[4][2], bl[4][2];
                #pragma unroll
                for (int pr = 0; pr < 2; pr++) {
                    uint32_t bo = (uint32_t)((wn*64 + half*32 + pr*16 + lrow) * PADK + kbase) * 2;
                    ldsm4(bh[pr*2][0], bh[pr*2+1][0], bh[pr*2][1], bh[pr*2+1][1], Bhb + bo);
                    ldsm4(bl[pr*2][0], bl[pr*2+1][0], bl[pr*2][1], bl[pr*2+1][1], Blb + bo);
                }
                #pragma unroll
                for (int mt = 0; mt < 2; mt++)
                    #pragma unroll
                    for (int nt = 0; nt < 4; nt++) {
                        float* cc = acc[mt][half * 4 + nt];
                        mma16816(cc, ah[mt], bh[nt]);
                        mma16816(cc, ah[mt], bl[nt]);
                        mma16816(cc, al[mt], bh[nt]);
                    }
            }
        }
        __syncthreads();
    }

    // ---- epilogue ----
    #pragma unroll
    for (int mt = 0; mt < 2; mt++) {
        int m_lo = row0 + wm * 32 + mt * 16 + gid;
        int m_hi = m_lo + 8;
        #pragma unroll
        for (int j = 0; j < 8; j++) {
            int nc = col0 + wn * 64 + (j >> 2) * 32 + (j & 3) * 8 + tig * 2;
            float b0 = bias[nc], b1 = bias[nc + 1];
            float* cc = acc[mt][j];
            float v0 = cc[0] + b0, v1 = cc[1] + b1;  // row m_lo
            float v2 = cc[2] + b0, v3 = cc[3] + b1;  // row m_hi
            if (mode == 0) {
                int which = (nc >= 2*DD) ? 2 : ((nc >= DD) ? 1 : 0);
                int rem = nc - which * DD;
                int h = rem >> 6, hs = rem & 63;
                int p0 = m_lo >> 10, n0 = m_lo & 1023;
                int p1 = m_hi >> 10, n1 = m_hi & 1023;
                int ph0 = p0 * HH + h, ph1 = p1 * HH + h;
                uint32_t whi, wlo;
                if (which == 2) {
                    size_t r0 = ((size_t)ph0 * HSZ + hs) * NN;
                    size_t r1 = ((size_t)ph1 * HSZ + hs) * NN;
                    split2(v0, v1, whi, wlo);
                    gVth[r0 + n0] = __ushort_as_bfloat16((unsigned short)(whi & 0xffff));
                    gVth[r0 + NN + n0] = __ushort_as_bfloat16((unsigned short)(whi >> 16));
                    gVtl[r0 + n0] = __ushort_as_bfloat16((unsigned short)(wlo & 0xffff));
                    gVtl[r0 + NN + n0] = __ushort_as_bfloat16((unsigned short)(wlo >> 16));
                    split2(v2, v3, whi, wlo);
                    gVth[r1 + n1] = __ushort_as_bfloat16((unsigned short)(whi & 0xffff));
                    gVth[r1 + NN + n1] = __ushort_as_bfloat16((unsigned short)(whi >> 16));
                    gVtl[r1 + n1] = __ushort_as_bfloat16((unsigned short)(wlo & 0xffff));
                    gVtl[r1 + NN + n1] = __ushort_as_bfloat16((unsigned short)(wlo >> 16));
                } else {
                    __nv_bfloat16* dh = which ? gKh : gQh;
                    __nv_bfloat16* dl = which ? gKl : gQl;
                    size_t o0 = (((size_t)ph0 << 10) + n0) * HSZ + hs;
                    size_t o1 = (((size_t)ph1 << 10) + n1) * HSZ + hs;
                    split2(v0, v1, whi, wlo);
                    *(uint32_t*)&dh[o0] = whi; *(uint32_t*)&dl[o0] = wlo;
                    split2(v2, v3, whi, wlo);
                    *(uint32_t*)&dh[o1] = whi; *(uint32_t*)&dl[o1] = wlo;
                }
            } else {
                *(float2*)&out[(size_t)m_lo * DD + nc] = make_float2(v0, v1);
                *(float2*)&out[(size_t)m_hi * DD + nc] = make_float2(v2, v3);
            }
        }
    }
}

// ================= post-softmax mask term =================
__global__ void maskv_kernel(const float* __restrict__ mask) {
    int ph = blockIdx.x;
    int p = ph / HH;
    int w = threadIdx.x >> 5, lane = threadIdx.x & 31;
    const float* mp = mask + (size_t)p * NN;
    #pragma unroll
    for (int i = 0; i < 8; i++) {
        int hs = w * 8 + i;
        const __nv_bfloat16* vh = gVth + ((size_t)ph * HSZ + hs) * NN;
        const __nv_bfloat16* vl = gVtl + ((size_t)ph * HSZ + hs) * NN;
        float acc = 0.f;
        for (int k = lane; k < NN; k += 32)
            acc += mp[k] * (__bfloat162float(vh[k]) + __bfloat162float(vl[k]));
        #pragma unroll
        for (int s = 16; s > 0; s >>= 1) acc += __shfl_xor_sync(0xffffffffu, acc, s);
        if (lane == 0) gMV[ph * HSZ + hs] = acc;
    }
}

// ================= flash attention via mma.sync + ldmatrix (bf16x3) =================
// CTA = (p, h, 256 q-rows), 512 threads = 16 warps x 16 q-rows.
// Buffer = 128 keys processed as two 64-key passes (no barrier between passes).
#define AKS 72
#define VKS 136
#define KT_B (128*AKS*2)            // 18432 B
#define VT_B (64*VKS*2)             // 17408 B
#define ABUF_B (2*KT_B + 2*VT_B)    // 71680 B
#define ATTN_SMEM (2*ABUF_B)        // 143360 B

__global__ __launch_bounds__(512, 1) void attn_mma() {
    extern __shared__ __align__(16) char smem[];
    uint32_t sb = smem_u32(smem);
    int tid = threadIdx.x, wid = tid >> 5, lane = tid & 31;
    int gid = lane >> 2, tig = lane & 3;
    int lrow = lane & 15, lcol8 = (lane >> 4) << 3;
    int qb = blockIdx.x, h = blockIdx.y, p = blockIdx.z;
    int ph = p * HH + h;
    int q0 = qb * 256 + wid * 16;    // warp's first q row

    // ---- preload Q fragments (hi/lo), warp rows q0 + {gid, gid+8}
    uint32_t qh[4][4], ql[4][4];
    {
        const __nv_bfloat16* base_h = gQh + ((size_t)ph * NN + q0) * HSZ;
        const __nv_bfloat16* base_l = gQl + ((size_t)ph * NN + q0) * HSZ;
        #pragma unroll
        for (int kk = 0; kk < 4; kk++) {
            int c = kk * 16 + tig * 2;
            qh[kk][0] = *(const uint32_t*)(base_h + (size_t)gid * HSZ + c);
            qh[kk][1] = *(const uint32_t*)(base_h + (size_t)(gid+8) * HSZ + c);
            qh[kk][2] = *(const uint32_t*)(base_h + (size_t)gid * HSZ + c + 8);
            qh[kk][3] = *(const uint32_t*)(base_h + (size_t)(gid+8) * HSZ + c + 8);
            ql[kk][0] = *(const uint32_t*)(base_l + (size_t)gid * HSZ + c);
            ql[kk][1] = *(const uint32_t*)(base_l + (size_t)(gid+8) * HSZ + c);
            ql[kk][2] = *(const uint32_t*)(base_l + (size_t)gid * HSZ + c + 8);
            ql[kk][3] = *(const uint32_t*)(base_l + (size_t)(gid+8) * HSZ + c + 8);
        }
    }

    float oacc[8][4];
    #pragma unroll
    for (int i = 0; i < 8; i++)
        #pragma unroll
        for (int j = 0; j < 4; j++) oacc[i][j] = 0.f;
    float m0 = -1e30f, m1 = -1e30f, l0 = 0.f, l1 = 0.f;

    const __nv_bfloat16* Kh_g = gKh + (size_t)ph * NN * HSZ;
    const __nv_bfloat16* Kl_g = gKl + (size_t)ph * NN * HSZ;
    const __nv_bfloat16* Vh_g = gVth + (size_t)ph * HSZ * NN;
    const __nv_bfloat16* Vl_g = gVtl + (size_t)ph * HSZ * NN;

    auto fill = [&](int s, int kb) {   // kb = 128-key block index (0..7)
        uint32_t base = sb + s * ABUF_B;
        #pragma unroll
        for (int j = 0; j < 2; j++) {
            int e = j * 512 + tid;
            int r = e >> 3, ch = e & 7;
            uint32_t d = base + (uint32_t)(r * AKS + ch * 8) * 2;
            const __nv_bfloat16* gh = Kh_g + (size_t)(kb*128 + r) * HSZ + ch * 8;
            const __nv_bfloat16* gl = Kl_g + (size_t)(kb*128 + r) * HSZ + ch * 8;
            CP16(d, gh);
            CP16(d + KT_B, gl);
        }
        #pragma unroll
        for (int j = 0; j < 2; j++) {
            int e = j * 512 + tid;
            int r = e >> 4, ch = e & 15;
            uint32_t d = base + 2*KT_B + (uint32_t)(r * VKS + ch * 8) * 2;
            const __nv_bfloat16* gh = Vh_g + (size_t)r * NN + kb*128 + ch * 8;
            const __nv_bfloat16* gl = Vl_g + (size_t)r * NN + kb*128 + ch * 8;
            CP16(d, gh);
            CP16(d + VT_B, gl);
        }
        CP_COMMIT();
    };

    fill(0, 0);
    for (int kb = 0; kb < 8; kb++) {
        if (kb < 7) fill((kb + 1) & 1, kb + 1);
        if (kb < 7) CP_WAIT1(); else CP_WAIT0();
        __syncthreads();

        uint32_t base = sb + (kb & 1) * ABUF_B;
        uint32_t Khb = base, Klb = base + KT_B;
        uint32_t Vhb = base + 2*KT_B, Vlb = Vhb + VT_B;

        #pragma unroll
        for (int pass = 0; pass < 2; pass++) {
            uint32_t kro = (uint32_t)(pass * 64 * AKS) * 2;   // K tile row offset
            uint32_t vco = (uint32_t)(pass * 64) * 2;         // Vt col offset

            // ---- S = Q K^T (16 x 64 per warp), 3-term hi/lo, ldmatrix fragments
            float sacc[8][4];
            #pragma unroll
            for (int nt = 0; nt < 8; nt++)
                #pragma unroll
                for (int j = 0; j < 4; j++) sacc[nt][j] = 0.f;
            #pragma unroll
            for (int kk = 0; kk < 4; kk++) {
                int kbase = kk * 16 + lcol8;
                #pragma unroll
                for (int g = 0; g < 2; g++) {      // nt groups of 4
                    uint32_t bh[4][2], bl[4][2];
                    #pragma unroll
                    for (int pr = 0; pr < 2; pr++) {
                        uint32_t bo = kro + (uint32_t)(((g*2+pr)*16 + lrow) * AKS + kbase) * 2;
                        ldsm4(bh[pr*2][0], bh[pr*2+1][0], bh[pr*2][1], bh[pr*2+1][1], Khb + bo);
                        ldsm4(bl[pr*2][0], bl[pr*2+1][0], bl[pr*2][1], bl[pr*2+1][1], Klb + bo);
                    }
                    #pragma unroll
                    for (int n4 = 0; n4 < 4; n4++) {
                        float* cc = sacc[g*4 + n4];
                        mma16816(cc, qh[kk], bh[n4]);
                        mma16816(cc, qh[kk], bl[n4]);
                        mma16816(cc, ql[kk], bh[n4]);
                    }
                }
            }

            // ---- online softmax
            float mx0 = -1e30f, mx1 = -1e30f;
            #pragma unroll
            for (int nt = 0; nt < 8; nt++) {
                mx0 = fmaxf(mx0, fmaxf(sacc[nt][0], sacc[nt][1]));
                mx1 = fmaxf(mx1, fmaxf(sacc[nt][2], sacc[nt][3]));
            }
            mx0 = fmaxf(mx0, __shfl_xor_sync(0xffffffffu, mx0, 1));
            mx0 = fmaxf(mx0, __shfl_xor_sync(0xffffffffu, mx0, 2));
            mx1 = fmaxf(mx1, __shfl_xor_sync(0xffffffffu, mx1, 1));
            mx1 = fmaxf(mx1, __shfl_xor_sync(0xffffffffu, mx1, 2));
            float nm0 = fmaxf(m0, mx0), nm1 = fmaxf(m1, mx1);
            float corr0 = exp2f((m0 - nm0) * SCLOG2);
            float corr1 = exp2f((m1 - nm1) * SCLOG2);
            m0 = nm0; m1 = nm1;
            float rs0 = 0.f, rs1 = 0.f;
            #pragma unroll
            for (int nt = 0; nt < 8; nt++) {
                sacc[nt][0] = exp2f((sacc[nt][0] - nm0) * SCLOG2);
                sacc[nt][1] = exp2f((sacc[nt][1] - nm0) * SCLOG2);
                sacc[nt][2] = exp2f((sacc[nt][2] - nm1) * SCLOG2);
                sacc[nt][3] = exp2f((sacc[nt][3] - nm1) * SCLOG2);
                rs0 += sacc[nt][0] + sacc[nt][1];
                rs1 += sacc[nt][2] + sacc[nt][3];
            }
            rs0 += __shfl_xor_sync(0xffffffffu, rs0, 1);
            rs0 += __shfl_xor_sync(0xffffffffu, rs0, 2);
            rs1 += __shfl_xor_sync(0xffffffffu, rs1, 1);
            rs1 += __shfl_xor_sync(0xffffffffu, rs1, 2);
            l0 = l0 * corr0 + rs0;
            l1 = l1 * corr1 + rs1;
            #pragma unroll
            for (int nt = 0; nt < 8; nt++) {
                oacc[nt][0] *= corr0; oacc[nt][1] *= corr0;
                oacc[nt][2] *= corr1; oacc[nt][3] *= corr1;
            }

            // ---- O += P V (ldmatrix V fragments)
            #pragma unroll
            for (int kblk = 0; kblk < 4; kblk++) {
                uint32_t ah[4], al[4];
                split2(sacc[2*kblk][0],   sacc[2*kblk][1],   ah[0], al[0]);
                split2(sacc[2*kblk][2],   sacc[2*kblk][3],   ah[1], al[1]);
                split2(sacc[2*kblk+1][0], sacc[2*kblk+1][1], ah[2], al[2]);
                split2(sacc[2*kblk+1][2], sacc[2*kblk+1][3], ah[3], al[3]);
                int kbase = kblk * 16 + lcol8;
                #pragma unroll
                for (int g = 0; g < 2; g++) {
                    uint32_t bh[4][2], bl[4][2];
                    #pragma unroll
                    for (int pr = 0; pr < 2; pr++) {
                        uint32_t bo = (uint32_t)(((g*2+pr)*16 + lrow) * VKS) * 2 + vco
                                    + (uint32_t)kbase * 2;
                        ldsm4(bh[pr*2][0], bh[pr*2+1][0], bh[pr*2][1], bh[pr*2+1][1], Vhb + bo);
                        ldsm4(bl[pr*2][0], bl[pr*2+1][0], bl[pr*2][1], bl[pr*2+1][1], Vlb + bo);
                    }
                    #pragma unroll
                    for (int n4 = 0; n4 < 4; n4++) {
                        float* cc = oacc[g*4 + n4];
                        mma16816(cc, ah, bh[n4]);
                        mma16816(cc, ah, bl[n4]);
                        mma16816(cc, al, bh[n4]);
                    }
                }
            }
        }
        __syncthreads();
    }

    // ---- epilogue: ctx = O/l + maskV, stored bf16 hi/lo
    float inv0 = 1.0f / l0, inv1 = 1.0f / l1;
    int q_lo = q0 + gid;
    int q_hi = q_lo + 8;
    #pragma unroll
    for (int nt = 0; nt < 8; nt++) {
        int hs = nt*8 + tig*2;
        float mv0 = gMV[ph*HSZ + hs], mv1 = gMV[ph*HSZ + hs + 1];
        float v0 = oacc[nt][0]*inv0 + mv0, v1 = oacc[nt][1]*inv0 + mv1;
        float v2 = oacc[nt][2]*inv1 + mv0, v3 = oacc[nt][3]*inv1 + mv1;
        size_t o0 = ((size_t)p*NN + q_lo) * DD + h*HSZ + hs;
        size_t o1 = ((size_t)p*NN + q_hi) * DD + h*HSZ + hs;
        uint32_t whi, wlo;
        split2(v0, v1, whi, wlo);
        *(uint32_t*)&gCh[o0] = whi; *(uint32_t*)&gCl[o0] = wlo;
        split2(v2, v3, whi, wlo);
        *(uint32_t*)&gCh[o1] = whi; *(uint32_t*)&gCl[o1] = wlo;
    }
}

extern "C" void kernel_launch(void* const* d_in, const int* in_sizes, int n_in,
                              void* d_out, int out_size) {
    const float* X      = (const float*)d_in[0];
    const float* mask   = (const float*)d_in[1];
    const float* qkv_w  = (const float*)d_in[2];
    const float* qkv_b  = (const float*)d_in[3];
    const float* proj_w = (const float*)d_in[4];
    const float* proj_b = (const float*)d_in[5];
    float* out = (float*)d_out;

    cudaFuncSetAttribute(gemm_mma, cudaFuncAttributeMaxDynamicSharedMemorySize, GEMM_SMEM);
    cudaFuncSetAttribute(attn_mma, cudaFuncAttributeMaxDynamicSharedMemorySize, ATTN_SMEM);

    __nv_bfloat16 *xhi, *xlo, *wqh, *wql, *wph, *wpl;
    cudaGetSymbolAddress((void**)&xhi, gXhi);
    cudaGetSymbolAddress((void**)&xlo, gXlo);
    cudaGetSymbolAddress((void**)&wqh, gWqh);
    cudaGetSymbolAddress((void**)&wql, gWql);
    cudaGetSymbolAddress((void**)&wph, gWph);
    cudaGetSymbolAddress((void**)&wpl, gWpl);

    split_kernel<<<(PP*NN*DD/4 + 255)/256, 256>>>(X, xhi, xlo, PP*NN*DD/4);
    tsplit_kernel<<<dim3(3*DD/32, DD/32), dim3(32,8)>>>(qkv_w, wqh, wql, DD, 3*DD);
    tsplit_kernel<<<dim3(DD/32, DD/32), dim3(32,8)>>>(proj_w, wph, wpl, DD, DD);
    gemm_mma<<<dim3(3*DD/256, PP*NN/128), 512, GEMM_SMEM>>>(0, qkv_b, nullptr);
    maskv_kernel<<<PP*HH, 256>>>(mask);
    attn_mma<<<dim3(NN/256, HH, PP), 512, ATTN_SMEM>>>();
    gemm_mma<<<dim3(DD/256, PP*NN/128), 512, GEMM_SMEM>>>(1, proj_b, out);
}

// round 9
// speedup vs baseline: 1.0569x; 1.0569x over previous
#include <cuda_runtime.h>
#include <cuda_bf16.h>
#include <cstdint>

#define PP 8
#define NN 1024
#define DD 768
#define HH 12
#define HSZ 64
#define SCLOG2 11.5423594967f   // 8 * log2(e)

// ---- scratch (static) ----
__device__ float gMV[PP*HH*HSZ];
__device__ __nv_bfloat16 gXhi[PP*NN*DD];
__device__ __nv_bfloat16 gXlo[PP*NN*DD];
__device__ __nv_bfloat16 gWqh[3*DD*DD];
__device__ __nv_bfloat16 gWql[3*DD*DD];
__device__ __nv_bfloat16 gWph[DD*DD];
__device__ __nv_bfloat16 gWpl[DD*DD];
__device__ __nv_bfloat16 gCh[PP*NN*DD];
__device__ __nv_bfloat16 gCl[PP*NN*DD];
// attention operands, bf16 hi/lo. Q,K: [ph][n][hs]; V transposed: [ph][hs][n]
__device__ __nv_bfloat16 gQh[PP*HH*NN*HSZ];
__device__ __nv_bfloat16 gQl[PP*HH*NN*HSZ];
__device__ __nv_bfloat16 gKh[PP*HH*NN*HSZ];
__device__ __nv_bfloat16 gKl[PP*HH*NN*HSZ];
__device__ __nv_bfloat16 gVth[PP*HH*NN*HSZ];
__device__ __nv_bfloat16 gVtl[PP*HH*NN*HSZ];

// ================= helpers =================
__device__ __forceinline__ uint32_t smem_u32(const void* p) {
    uint32_t a;
    asm("{ .reg .u64 t; cvta.to.shared.u64 t, %1; cvt.u32.u64 %0, t; }" : "=r"(a) : "l"(p));
    return a;
}
__device__ __forceinline__ uint32_t lds32(uint32_t a) {
    uint32_t v;
    asm volatile("ld.shared.b32 %0, [%1];" : "=r"(v) : "r"(a));
    return v;
}
#define CP16(saddr, gptr) \
    asm volatile("cp.async.cg.shared.global [%0], [%1], 16;" :: "r"(saddr), "l"(gptr))
#define CP_COMMIT() asm volatile("cp.async.commit_group;" ::: "memory")
#define CP_WAIT1()  asm volatile("cp.async.wait_group 1;" ::: "memory")
#define CP_WAIT0()  asm volatile("cp.async.wait_group 0;" ::: "memory")

__device__ __forceinline__ void mma16816(float* c, const uint32_t* a, const uint32_t* b) {
    asm volatile("mma.sync.aligned.m16n8k16.row.col.f32.bf16.bf16.f32 "
                 "{%0,%1,%2,%3}, {%4,%5,%6,%7}, {%8,%9}, {%0,%1,%2,%3};"
                 : "+f"(c[0]), "+f"(c[1]), "+f"(c[2]), "+f"(c[3])
                 : "r"(a[0]), "r"(a[1]), "r"(a[2]), "r"(a[3]), "r"(b[0]), "r"(b[1]));
}
// pack two floats -> bf16x2 (v0 in low half)
__device__ __forceinline__ uint32_t pack2(float v0, float v1) {
    uint32_t r;
    asm("cvt.rn.bf16x2.f32 %0, %1, %2;" : "=r"(r) : "f"(v1), "f"(v0));
    return r;
}
// hi/lo split of a float pair into two bf16x2 words
__device__ __forceinline__ void split2(float v0, float v1, uint32_t& phi, uint32_t& plo) {
    phi = pack2(v0, v1);
    float h0 = __uint_as_float(phi << 16);
    float h1 = __uint_as_float(phi & 0xffff0000u);
    plo = pack2(v0 - h0, v1 - h1);
}

// ================= split / transpose-split =================
__global__ void split_kernel(const float* __restrict__ src,
                             __nv_bfloat16* __restrict__ hi,
                             __nv_bfloat16* __restrict__ lo, int n4) {
    int i = blockIdx.x * blockDim.x + threadIdx.x;
    if (i >= n4) return;
    float4 v = ((const float4*)src)[i];
    uint32_t h[2], l[2];
    split2(v.x, v.y, h[0], l[0]);
    split2(v.z, v.w, h[1], l[1]);
    ((uint2*)hi)[i] = make_uint2(h[0], h[1]);
    ((uint2*)lo)[i] = make_uint2(l[0], l[1]);
}

__global__ void tsplit_kernel(const float* __restrict__ W,
                              __nv_bfloat16* __restrict__ Th,
                              __nv_bfloat16* __restrict__ Tl, int K, int N) {
    __shared__ float t[32][33];
    int k0 = blockIdx.y * 32, n0 = blockIdx.x * 32;
    int tx = threadIdx.x, ty = threadIdx.y;
    #pragma unroll
    for (int i = 0; i < 4; i++)
        t[ty + 8*i][tx] = W[(size_t)(k0 + ty + 8*i) * N + n0 + tx];
    __syncthreads();
    #pragma unroll
    for (int i = 0; i < 4; i++) {
        float x = t[tx][ty + 8*i];
        __nv_bfloat16 h = __float2bfloat16_rn(x);
        __nv_bfloat16 l = __float2bfloat16_rn(x - __bfloat162float(h));
        size_t o = (size_t)(n0 + ty + 8*i) * K + k0 + tx;
        Th[o] = h; Tl[o] = l;
    }
}

// ================= bf16x3 GEMM via mma.sync =================
// CTA tile 128(m) x 128(n), 256 threads (8 warps = 4m x 2n, warp tile 32x64),
// K-chunk 32, double-buffered cp.async, 2 CTAs/SM.
#define PADK 40
#define TILE_E (128*PADK)
#define BUF_BYTES (4*TILE_E*2)       // 40960 B per buffer
#define GEMM_SMEM (2*BUF_BYTES)      // 81920 B

__global__ __launch_bounds__(256, 2) void gemm_mma(int mode,
                                                   const float* __restrict__ bias,
                                                   float* __restrict__ out) {
    extern __shared__ __align__(16) char smem[];
    uint32_t sb = smem_u32(smem);
    int tid = threadIdx.x, wid = tid >> 5, lane = tid & 31;
    int wm = wid & 3, wn = wid >> 2;
    int row0 = blockIdx.y * 128, col0 = blockIdx.x * 128;
    int gid = lane >> 2, tig = lane & 3;

    const __nv_bfloat16* Ah = mode ? gCh : gXhi;
    const __nv_bfloat16* Al = mode ? gCl : gXlo;
    const __nv_bfloat16* Bh = mode ? gWph : gWqh;
    const __nv_bfloat16* Bl = mode ? gWpl : gWql;
    const __nv_bfloat16* srcs[4] = {Ah, Al, Bh, Bl};

    float acc[2][8][4];
    #pragma unroll
    for (int i = 0; i < 2; i++)
        #pragma unroll
        for (int j = 0; j < 8; j++)
            #pragma unroll
            for (int q = 0; q < 4; q++) acc[i][j][q] = 0.f;

    auto fill = [&](int s, int c) {
        int k0 = c * 32;
        uint32_t sbase = sb + s * BUF_BYTES;
        #pragma unroll
        for (int t = 0; t < 4; t++) {
            const __nv_bfloat16* src = srcs[t];
            int rbase = (t < 2) ? row0 : col0;
            #pragma unroll
            for (int j = 0; j < 2; j++) {
                int e = j * 256 + tid;
                int r = e >> 2, v = e & 3;
                uint32_t daddr = sbase + (uint32_t)(t * TILE_E + r * PADK + v * 8) * 2;
                const __nv_bfloat16* g = src + (size_t)(rbase + r) * DD + k0 + v * 8;
                CP16(daddr, g);
            }
        }
        CP_COMMIT();
    };

    fill(0, 0);
    for (int c = 0; c < 24; c++) {
        if (c < 23) fill((c + 1) & 1, c + 1);
        if (c < 23) CP_WAIT1(); else CP_WAIT0();
        __syncthreads();

        uint32_t base = sb + (c & 1) * BUF_BYTES;
        uint32_t Ahb = base, Alb = base + TILE_E*2;
        uint32_t Bhb = base + 2*TILE_E*2, Blb = Bhb + TILE_E*2;

        #pragma unroll
        for (int ks = 0; ks < 2; ks++) {
            int kcol = ks * 16 + tig * 2;
            uint32_t ah[2][4], al[2][4];
            #pragma unroll
            for (int mt = 0; mt < 2; mt++) {
                int r = wm * 32 + mt * 16 + gid;
                uint32_t o = (uint32_t)(r * PADK + kcol) * 2;
                ah[mt][0] = lds32(Ahb + o);
                ah[mt][1] = lds32(Ahb + o + 8*PADK*2);
                ah[mt][2] = lds32(Ahb + o + 16);
                ah[mt][3] = lds32(Ahb + o + 8*PADK*2 + 16);
                al[mt][0] = lds32(Alb + o);
                al[mt][1] = lds32(Alb + o + 8*PADK*2);
                al[mt][2] = lds32(Alb + o + 16);
                al[mt][3] = lds32(Alb + o + 8*PADK*2 + 16);
            }
            #pragma unroll
            for (int half = 0; half < 2; half++) {
                uint32_t bh[4][2], bl[4][2];
                #pragma unroll
                for (int nt = 0; nt < 4; nt++) {
                    int n = wn * 64 + half * 32 + nt * 8 + gid;
                    uint32_t o = (uint32_t)(n * PADK + kcol) * 2;
                    bh[nt][0] = lds32(Bhb + o);
                    bh[nt][1] = lds32(Bhb + o + 16);
                    bl[nt][0] = lds32(Blb + o);
                    bl[nt][1] = lds32(Blb + o + 16);
                }
                #pragma unroll
                for (int mt = 0; mt < 2; mt++)
                    #pragma unroll
                    for (int nt = 0; nt < 4; nt++) {
                        float* cc = acc[mt][half * 4 + nt];
                        mma16816(cc, ah[mt], bh[nt]);
                        mma16816(cc, ah[mt], bl[nt]);
                        mma16816(cc, al[mt], bh[nt]);
                    }
            }
        }
        __syncthreads();
    }

    // ---- epilogue ----
    #pragma unroll
    for (int mt = 0; mt < 2; mt++) {
        int m_lo = row0 + wm * 32 + mt * 16 + gid;
        int m_hi = m_lo + 8;
        #pragma unroll
        for (int j = 0; j < 8; j++) {
            int nc = col0 + wn * 64 + (j >> 2) * 32 + (j & 3) * 8 + tig * 2;
            float b0 = bias[nc], b1 = bias[nc + 1];
            float* cc = acc[mt][j];
            float v0 = cc[0] + b0, v1 = cc[1] + b1;  // row m_lo
            float v2 = cc[2] + b0, v3 = cc[3] + b1;  // row m_hi
            if (mode == 0) {
                int which = (nc >= 2*DD) ? 2 : ((nc >= DD) ? 1 : 0);
                int rem = nc - which * DD;
                int h = rem >> 6, hs = rem & 63;
                int p0 = m_lo >> 10, n0 = m_lo & 1023;
                int p1 = m_hi >> 10, n1 = m_hi & 1023;
                int ph0 = p0 * HH + h, ph1 = p1 * HH + h;
                uint32_t whi, wlo;
                if (which == 2) {
                    size_t r0 = ((size_t)ph0 * HSZ + hs) * NN;
                    size_t r1 = ((size_t)ph1 * HSZ + hs) * NN;
                    split2(v0, v1, whi, wlo);
                    gVth[r0 + n0] = __ushort_as_bfloat16((unsigned short)(whi & 0xffff));
                    gVth[r0 + NN + n0] = __ushort_as_bfloat16((unsigned short)(whi >> 16));
                    gVtl[r0 + n0] = __ushort_as_bfloat16((unsigned short)(wlo & 0xffff));
                    gVtl[r0 + NN + n0] = __ushort_as_bfloat16((unsigned short)(wlo >> 16));
                    split2(v2, v3, whi, wlo);
                    gVth[r1 + n1] = __ushort_as_bfloat16((unsigned short)(whi & 0xffff));
                    gVth[r1 + NN + n1] = __ushort_as_bfloat16((unsigned short)(whi >> 16));
                    gVtl[r1 + n1] = __ushort_as_bfloat16((unsigned short)(wlo & 0xffff));
                    gVtl[r1 + NN + n1] = __ushort_as_bfloat16((unsigned short)(wlo >> 16));
                } else {
                    __nv_bfloat16* dh = which ? gKh : gQh;
                    __nv_bfloat16* dl = which ? gKl : gQl;
                    size_t o0 = (((size_t)ph0 << 10) + n0) * HSZ + hs;
                    size_t o1 = (((size_t)ph1 << 10) + n1) * HSZ + hs;
                    split2(v0, v1, whi, wlo);
                    *(uint32_t*)&dh[o0] = whi; *(uint32_t*)&dl[o0] = wlo;
                    split2(v2, v3, whi, wlo);
                    *(uint32_t*)&dh[o1] = whi; *(uint32_t*)&dl[o1] = wlo;
                }
            } else {
                *(float2*)&out[(size_t)m_lo * DD + nc] = make_float2(v0, v1);
                *(float2*)&out[(size_t)m_hi * DD + nc] = make_float2(v2, v3);
            }
        }
    }
}

// ================= post-softmax mask term =================
__global__ void maskv_kernel(const float* __restrict__ mask) {
    int ph = blockIdx.x;
    int p = ph / HH;
    int w = threadIdx.x >> 5, lane = threadIdx.x & 31;
    const float* mp = mask + (size_t)p * NN;
    #pragma unroll
    for (int i = 0; i < 8; i++) {
        int hs = w * 8 + i;
        const __nv_bfloat16* vh = gVth + ((size_t)ph * HSZ + hs) * NN;
        const __nv_bfloat16* vl = gVtl + ((size_t)ph * HSZ + hs) * NN;
        float acc = 0.f;
        for (int k = lane; k < NN; k += 32)
            acc += mp[k] * (__bfloat162float(vh[k]) + __bfloat162float(vl[k]));
        #pragma unroll
        for (int s = 16; s > 0; s >>= 1) acc += __shfl_xor_sync(0xffffffffu, acc, s);
        if (lane == 0) gMV[ph * HSZ + hs] = acc;
    }
}

// ================= flash attention via mma.sync (bf16x3) =================
// CTA = (p, h, 128 q-rows), 256 threads = 8 warps x 16 q-rows.
// K-block 64, double buffered, 2 CTAs/SM.
// smem per buffer: Kh[64][72], Kl, Vth[64][72], Vtl
#define AKS 72
#define KTILE_B (64*AKS*2)          // 9216 B
#define ABUF_B (4*KTILE_B)          // 36864 B
#define ATTN_SMEM (2*ABUF_B)        // 73728 B

__global__ __launch_bounds__(256, 2) void attn_mma() {
    extern __shared__ __align__(16) char smem[];
    uint32_t sb = smem_u32(smem);
    int tid = threadIdx.x, wid = tid >> 5, lane = tid & 31;
    int gid = lane >> 2, tig = lane & 3;
    int qb = blockIdx.x, h = blockIdx.y, p = blockIdx.z;
    int ph = p * HH + h;
    int q0 = qb * 128 + wid * 16;    // warp's first q row

    // ---- preload Q fragments (hi/lo), warp rows q0 + {gid, gid+8}
    uint32_t qh[4][4], ql[4][4];
    {
        const __nv_bfloat16* base_h = gQh + ((size_t)ph * NN + q0) * HSZ;
        const __nv_bfloat16* base_l = gQl + ((size_t)ph * NN + q0) * HSZ;
        #pragma unroll
        for (int kk = 0; kk < 4; kk++) {
            int c = kk * 16 + tig * 2;
            qh[kk][0] = *(const uint32_t*)(base_h + (size_t)gid * HSZ + c);
            qh[kk][1] = *(const uint32_t*)(base_h + (size_t)(gid+8) * HSZ + c);
            qh[kk][2] = *(const uint32_t*)(base_h + (size_t)gid * HSZ + c + 8);
            qh[kk][3] = *(const uint32_t*)(base_h + (size_t)(gid+8) * HSZ + c + 8);
            ql[kk][0] = *(const uint32_t*)(base_l + (size_t)gid * HSZ + c);
            ql[kk][1] = *(const uint32_t*)(base_l + (size_t)(gid+8) * HSZ + c);
            ql[kk][2] = *(const uint32_t*)(base_l + (size_t)gid * HSZ + c + 8);
            ql[kk][3] = *(const uint32_t*)(base_l + (size_t)(gid+8) * HSZ + c + 8);
        }
    }

    float oacc[8][4];
    #pragma unroll
    for (int i = 0; i < 8; i++)
        #pragma unroll
        for (int j = 0; j < 4; j++) oacc[i][j] = 0.f;
    float m0 = -1e30f, m1 = -1e30f, l0 = 0.f, l1 = 0.f;

    const __nv_bfloat16* Kh_g = gKh + (size_t)ph * NN * HSZ;
    const __nv_bfloat16* Kl_g = gKl + (size_t)ph * NN * HSZ;
    const __nv_bfloat16* Vh_g = gVth + (size_t)ph * HSZ * NN;
    const __nv_bfloat16* Vl_g = gVtl + (size_t)ph * HSZ * NN;

    auto fill = [&](int s, int kb) {
        uint32_t base = sb + s * ABUF_B;
        // K tile: 64 keys x 64 hs (512 x 16B chunks per type)
        #pragma unroll
        for (int j = 0; j < 2; j++) {
            int e = j * 256 + tid;
            int r = e >> 3, ch = e & 7;
            uint32_t d = base + (uint32_t)(r * AKS + ch * 8) * 2;
            const __nv_bfloat16* gh = Kh_g + (size_t)(kb*64 + r) * HSZ + ch * 8;
            const __nv_bfloat16* gl = Kl_g + (size_t)(kb*64 + r) * HSZ + ch * 8;
            CP16(d, gh);
            CP16(d + KTILE_B, gl);
        }
        // Vt tile: 64 hs x 64 keys (512 x 16B chunks per type)
        #pragma unroll
        for (int j = 0; j < 2; j++) {
            int e = j * 256 + tid;
            int r = e >> 3, ch = e & 7;
            uint32_t d = base + 2*KTILE_B + (uint32_t)(r * AKS + ch * 8) * 2;
            const __nv_bfloat16* gh = Vh_g + (size_t)r * NN + kb*64 + ch * 8;
            const __nv_bfloat16* gl = Vl_g + (size_t)r * NN + kb*64 + ch * 8;
            CP16(d, gh);
            CP16(d + KTILE_B, gl);
        }
        CP_COMMIT();
    };

    fill(0, 0);
    for (int kb = 0; kb < 16; kb++) {
        if (kb < 15) fill((kb + 1) & 1, kb + 1);
        if (kb < 15) CP_WAIT1(); else CP_WAIT0();
        __syncthreads();

        uint32_t base = sb + (kb & 1) * ABUF_B;
        uint32_t Khb = base, Klb = base + KTILE_B;
        uint32_t Vhb = base + 2*KTILE_B, Vlb = base + 3*KTILE_B;

        // ---- S = Q K^T (16 x 64 per warp), 3-term hi/lo
        float sacc[8][4];
        #pragma unroll
        for (int nt = 0; nt < 8; nt++) {
            #pragma unroll
            for (int j = 0; j < 4; j++) sacc[nt][j] = 0.f;
            uint32_t ro = (uint32_t)((nt*8 + gid) * AKS) * 2;
            #pragma unroll
            for (int kk = 0; kk < 4; kk++) {
                uint32_t co = (uint32_t)(kk*16 + tig*2) * 2;
                uint32_t bh[2], bl[2];
                bh[0] = lds32(Khb + ro + co);
                bh[1] = lds32(Khb + ro + co + 16);
                bl[0] = lds32(Klb + ro + co);
                bl[1] = lds32(Klb + ro + co + 16);
                mma16816(sacc[nt], qh[kk], bh);
                mma16816(sacc[nt], qh[kk], bl);
                mma16816(sacc[nt], ql[kk], bh);
            }
        }

        // ---- online softmax (scale x8 folded into exp2 constant)
        float mx0 = -1e30f, mx1 = -1e30f;
        #pragma unroll
        for (int nt = 0; nt < 8; nt++) {
            mx0 = fmaxf(mx0, fmaxf(sacc[nt][0], sacc[nt][1]));
            mx1 = fmaxf(mx1, fmaxf(sacc[nt][2], sacc[nt][3]));
        }
        mx0 = fmaxf(mx0, __shfl_xor_sync(0xffffffffu, mx0, 1));
        mx0 = fmaxf(mx0, __shfl_xor_sync(0xffffffffu, mx0, 2));
        mx1 = fmaxf(mx1, __shfl_xor_sync(0xffffffffu, mx1, 1));
        mx1 = fmaxf(mx1, __shfl_xor_sync(0xffffffffu, mx1, 2));
        float nm0 = fmaxf(m0, mx0), nm1 = fmaxf(m1, mx1);
        float corr0 = exp2f((m0 - nm0) * SCLOG2);
        float corr1 = exp2f((m1 - nm1) * SCLOG2);
        m0 = nm0; m1 = nm1;
        float rs0 = 0.f, rs1 = 0.f;
        #pragma unroll
        for (int nt = 0; nt < 8; nt++) {
            sacc[nt][0] = exp2f((sacc[nt][0] - nm0) * SCLOG2);
            sacc[nt][1] = exp2f((sacc[nt][1] - nm0) * SCLOG2);
            sacc[nt][2] = exp2f((sacc[nt][2] - nm1) * SCLOG2);
            sacc[nt][3] = exp2f((sacc[nt][3] - nm1) * SCLOG2);
            rs0 += sacc[nt][0] + sacc[nt][1];
            rs1 += sacc[nt][2] + sacc[nt][3];
        }
        rs0 += __shfl_xor_sync(0xffffffffu, rs0, 1);
        rs0 += __shfl_xor_sync(0xffffffffu, rs0, 2);
        rs1 += __shfl_xor_sync(0xffffffffu, rs1, 1);
        rs1 += __shfl_xor_sync(0xffffffffu, rs1, 2);
        l0 = l0 * corr0 + rs0;
        l1 = l1 * corr1 + rs1;
        #pragma unroll
        for (int nt = 0; nt < 8; nt++) {
            oacc[nt][0] *= corr0; oacc[nt][1] *= corr0;
            oacc[nt][2] *= corr1; oacc[nt][3] *= corr1;
        }

        // ---- O += P V, P in registers (hi/lo), V from smem
        #pragma unroll
        for (int kblk = 0; kblk < 4; kblk++) {
            uint32_t ah[4], al[4];
            split2(sacc[2*kblk][0],   sacc[2*kblk][1],   ah[0], al[0]);
            split2(sacc[2*kblk][2],   sacc[2*kblk][3],   ah[1], al[1]);
            split2(sacc[2*kblk+1][0], sacc[2*kblk+1][1], ah[2], al[2]);
            split2(sacc[2*kblk+1][2], sacc[2*kblk+1][3], ah[3], al[3]);
            uint32_t co = (uint32_t)(kblk*16 + tig*2) * 2;
            #pragma unroll
            for (int nt = 0; nt < 8; nt++) {
                uint32_t ro = (uint32_t)((nt*8 + gid) * AKS) * 2;
                uint32_t bh[2], bl[2];
                bh[0] = lds32(Vhb + ro + co);
                bh[1] = lds32(Vhb + ro + co + 16);
                bl[0] = lds32(Vlb + ro + co);
                bl[1] = lds32(Vlb + ro + co + 16);
                mma16816(oacc[nt], ah, bh);
                mma16816(oacc[nt], ah, bl);
                mma16816(oacc[nt], al, bh);
            }
        }
        __syncthreads();
    }

    // ---- epilogue: ctx = O/l + maskV, stored bf16 hi/lo
    float inv0 = 1.0f / l0, inv1 = 1.0f / l1;
    int q_lo = q0 + gid;
    int q_hi = q_lo + 8;
    #pragma unroll
    for (int nt = 0; nt < 8; nt++) {
        int hs = nt*8 + tig*2;
        float mv0 = gMV[ph*HSZ + hs], mv1 = gMV[ph*HSZ + hs + 1];
        float v0 = oacc[nt][0]*inv0 + mv0, v1 = oacc[nt][1]*inv0 + mv1;
        float v2 = oacc[nt][2]*inv1 + mv0, v3 = oacc[nt][3]*inv1 + mv1;
        size_t o0 = ((size_t)p*NN + q_lo) * DD + h*HSZ + hs;
        size_t o1 = ((size_t)p*NN + q_hi) * DD + h*HSZ + hs;
        uint32_t whi, wlo;
        split2(v0, v1, whi, wlo);
        *(uint32_t*)&gCh[o0] = whi; *(uint32_t*)&gCl[o0] = wlo;
        split2(v2, v3, whi, wlo);
        *(uint32_t*)&gCh[o1] = whi; *(uint32_t*)&gCl[o1] = wlo;
    }
}

extern "C" void kernel_launch(void* const* d_in, const int* in_sizes, int n_in,
                              void* d_out, int out_size) {
    const float* X      = (const float*)d_in[0];
    const float* mask   = (const float*)d_in[1];
    const float* qkv_w  = (const float*)d_in[2];
    const float* qkv_b  = (const float*)d_in[3];
    const float* proj_w = (const float*)d_in[4];
    const float* proj_b = (const float*)d_in[5];
    float* out = (float*)d_out;

    cudaFuncSetAttribute(gemm_mma, cudaFuncAttributeMaxDynamicSharedMemorySize, GEMM_SMEM);
    cudaFuncSetAttribute(attn_mma, cudaFuncAttributeMaxDynamicSharedMemorySize, ATTN_SMEM);

    __nv_bfloat16 *xhi, *xlo, *wqh, *wql, *wph, *wpl;
    cudaGetSymbolAddress((void**)&xhi, gXhi);
    cudaGetSymbolAddress((void**)&xlo, gXlo);
    cudaGetSymbolAddress((void**)&wqh, gWqh);
    cudaGetSymbolAddress((void**)&wql, gWql);
    cudaGetSymbolAddress((void**)&wph, gWph);
    cudaGetSymbolAddress((void**)&wpl, gWpl);

    split_kernel<<<(PP*NN*DD/4 + 255)/256, 256>>>(X, xhi, xlo, PP*NN*DD/4);
    tsplit_kernel<<<dim3(3*DD/32, DD/32), dim3(32,8)>>>(qkv_w, wqh, wql, DD, 3*DD);
    tsplit_kernel<<<dim3(DD/32, DD/32), dim3(32,8)>>>(proj_w, wph, wpl, DD, DD);
    gemm_mma<<<dim3(3*DD/128, PP*NN/128), 256, GEMM_SMEM>>>(0, qkv_b, nullptr);
    maskv_kernel<<<PP*HH, 256>>>(mask);
    attn_mma<<<dim3(NN/128, HH, PP), 256, ATTN_SMEM>>>();
    gemm_mma<<<dim3(DD/128, PP*NN/128), 256, GEMM_SMEM>>>(1, proj_b, out);
}

// round 12
// speedup vs baseline: 1.0631x; 1.0059x over previous
#include <cuda_runtime.h>
#include <cuda_bf16.h>
#include <cstdint>

#define PP 8
#define NN 1024
#define DD 768
#define HH 12
#define HSZ 64
#define SCLOG2 11.5423594967f   // 8 * log2(e)

// ---- scratch (static) ----
__device__ float gMV[PP*HH*HSZ];
__device__ __nv_bfloat16 gXhi[PP*NN*DD];
__device__ __nv_bfloat16 gXlo[PP*NN*DD];
__device__ __nv_bfloat16 gWqh[3*DD*DD];
__device__ __nv_bfloat16 gWql[3*DD*DD];
__device__ __nv_bfloat16 gWph[DD*DD];
__device__ __nv_bfloat16 gWpl[DD*DD];
__device__ __nv_bfloat16 gCh[PP*NN*DD];
__device__ __nv_bfloat16 gCl[PP*NN*DD];
// attention operands, bf16 hi/lo. Q,K: [ph][n][hs]; V transposed: [ph][hs][n]
__device__ __nv_bfloat16 gQh[PP*HH*NN*HSZ];
__device__ __nv_bfloat16 gQl[PP*HH*NN*HSZ];
__device__ __nv_bfloat16 gKh[PP*HH*NN*HSZ];
__device__ __nv_bfloat16 gKl[PP*HH*NN*HSZ];
__device__ __nv_bfloat16 gVth[PP*HH*NN*HSZ];
__device__ __nv_bfloat16 gVtl[PP*HH*NN*HSZ];

// ================= helpers =================
__device__ __forceinline__ uint32_t smem_u32(const void* p) {
    uint32_t a;
    asm("{ .reg .u64 t; cvta.to.shared.u64 t, %1; cvt.u32.u64 %0, t; }" : "=r"(a) : "l"(p));
    return a;
}
__device__ __forceinline__ uint32_t lds32(uint32_t a) {
    uint32_t v;
    asm volatile("ld.shared.b32 %0, [%1];" : "=r"(v) : "r"(a));
    return v;
}
#define CP16(saddr, gptr) \
    asm volatile("cp.async.cg.shared.global [%0], [%1], 16;" :: "r"(saddr), "l"(gptr))
#define CP_COMMIT() asm volatile("cp.async.commit_group;" ::: "memory")
#define CP_WAIT1()  asm volatile("cp.async.wait_group 1;" ::: "memory")
#define CP_WAIT0()  asm volatile("cp.async.wait_group 0;" ::: "memory")

__device__ __forceinline__ void mma16816(float* c, const uint32_t* a, const uint32_t* b) {
    asm volatile("mma.sync.aligned.m16n8k16.row.col.f32.bf16.bf16.f32 "
                 "{%0,%1,%2,%3}, {%4,%5,%6,%7}, {%8,%9}, {%0,%1,%2,%3};"
                 : "+f"(c[0]), "+f"(c[1]), "+f"(c[2]), "+f"(c[3])
                 : "r"(a[0]), "r"(a[1]), "r"(a[2]), "r"(a[3]), "r"(b[0]), "r"(b[1]));
}
// pack two floats -> bf16x2 (v0 in low half)
__device__ __forceinline__ uint32_t pack2(float v0, float v1) {
    uint32_t r;
    asm("cvt.rn.bf16x2.f32 %0, %1, %2;" : "=r"(r) : "f"(v1), "f"(v0));
    return r;
}
// hi/lo split of a float pair into two bf16x2 words
__device__ __forceinline__ void split2(float v0, float v1, uint32_t& phi, uint32_t& plo) {
    phi = pack2(v0, v1);
    float h0 = __uint_as_float(phi << 16);
    float h1 = __uint_as_float(phi & 0xffff0000u);
    plo = pack2(v0 - h0, v1 - h1);
}

// ================= split / transpose-split =================
__global__ void split_kernel(const float* __restrict__ src,
                             __nv_bfloat16* __restrict__ hi,
                             __nv_bfloat16* __restrict__ lo, int n4) {
    int i = blockIdx.x * blockDim.x + threadIdx.x;
    if (i >= n4) return;
    float4 v = ((const float4*)src)[i];
    uint32_t h[2], l[2];
    split2(v.x, v.y, h[0], l[0]);
    split2(v.z, v.w, h[1], l[1]);
    ((uint2*)hi)[i] = make_uint2(h[0], h[1]);
    ((uint2*)lo)[i] = make_uint2(l[0], l[1]);
}

__global__ void tsplit_kernel(const float* __restrict__ W,
                              __nv_bfloat16* __restrict__ Th,
                              __nv_bfloat16* __restrict__ Tl, int K, int N) {
    __shared__ float t[32][33];
    int k0 = blockIdx.y * 32, n0 = blockIdx.x * 32;
    int tx = threadIdx.x, ty = threadIdx.y;
    #pragma unroll
    for (int i = 0; i < 4; i++)
        t[ty + 8*i][tx] = W[(size_t)(k0 + ty + 8*i) * N + n0 + tx];
    __syncthreads();
    #pragma unroll
    for (int i = 0; i < 4; i++) {
        float x = t[tx][ty + 8*i];
        __nv_bfloat16 h = __float2bfloat16_rn(x);
        __nv_bfloat16 l = __float2bfloat16_rn(x - __bfloat162float(h));
        size_t o = (size_t)(n0 + ty + 8*i) * K + k0 + tx;
        Th[o] = h; Tl[o] = l;
    }
}

// ================= bf16x3 GEMM via mma.sync =================
// CTA tile 128(m) x 128(n), 256 threads (8 warps = 4m x 2n, warp tile 32x64),
// K-chunk 32, double-buffered cp.async, 2 CTAs/SM. Term-major MMA issue.
#define PADK 40
#define TILE_E (128*PADK)
#define BUF_BYTES (4*TILE_E*2)       // 40960 B per buffer
#define GEMM_SMEM (2*BUF_BYTES)      // 81920 B

__global__ __launch_bounds__(256, 2) void gemm_mma(int mode,
                                                   const float* __restrict__ bias,
                                                   float* __restrict__ out) {
    extern __shared__ __align__(16) char smem[];
    uint32_t sb = smem_u32(smem);
    int tid = threadIdx.x, wid = tid >> 5, lane = tid & 31;
    int wm = wid & 3, wn = wid >> 2;
    int row0 = blockIdx.y * 128, col0 = blockIdx.x * 128;
    int gid = lane >> 2, tig = lane & 3;

    const __nv_bfloat16* Ah = mode ? gCh : gXhi;
    const __nv_bfloat16* Al = mode ? gCl : gXlo;
    const __nv_bfloat16* Bh = mode ? gWph : gWqh;
    const __nv_bfloat16* Bl = mode ? gWpl : gWql;
    const __nv_bfloat16* srcs[4] = {Ah, Al, Bh, Bl};

    float acc[2][8][4];
    #pragma unroll
    for (int i = 0; i < 2; i++)
        #pragma unroll
        for (int j = 0; j < 8; j++)
            #pragma unroll
            for (int q = 0; q < 4; q++) acc[i][j][q] = 0.f;

    auto fill = [&](int s, int c) {
        int k0 = c * 32;
        uint32_t sbase = sb + s * BUF_BYTES;
        #pragma unroll
        for (int t = 0; t < 4; t++) {
            const __nv_bfloat16* src = srcs[t];
            int rbase = (t < 2) ? row0 : col0;
            #pragma unroll
            for (int j = 0; j < 2; j++) {
                int e = j * 256 + tid;
                int r = e >> 2, v = e & 3;
                uint32_t daddr = sbase + (uint32_t)(t * TILE_E + r * PADK + v * 8) * 2;
                const __nv_bfloat16* g = src + (size_t)(rbase + r) * DD + k0 + v * 8;
                CP16(daddr, g);
            }
        }
        CP_COMMIT();
    };

    fill(0, 0);
    for (int c = 0; c < 24; c++) {
        if (c < 23) fill((c + 1) & 1, c + 1);
        if (c < 23) CP_WAIT1(); else CP_WAIT0();
        __syncthreads();

        uint32_t base = sb + (c & 1) * BUF_BYTES;
        uint32_t Ahb = base, Alb = base + TILE_E*2;
        uint32_t Bhb = base + 2*TILE_E*2, Blb = Bhb + TILE_E*2;

        #pragma unroll
        for (int ks = 0; ks < 2; ks++) {
            int kcol = ks * 16 + tig * 2;
            uint32_t ah[2][4], al[2][4];
            #pragma unroll
            for (int mt = 0; mt < 2; mt++) {
                int r = wm * 32 + mt * 16 + gid;
                uint32_t o = (uint32_t)(r * PADK + kcol) * 2;
                ah[mt][0] = lds32(Ahb + o);
                ah[mt][1] = lds32(Ahb + o + 8*PADK*2);
                ah[mt][2] = lds32(Ahb + o + 16);
                ah[mt][3] = lds32(Ahb + o + 8*PADK*2 + 16);
                al[mt][0] = lds32(Alb + o);
                al[mt][1] = lds32(Alb + o + 8*PADK*2);
                al[mt][2] = lds32(Alb + o + 16);
                al[mt][3] = lds32(Alb + o + 8*PADK*2 + 16);
            }
            #pragma unroll
            for (int half = 0; half < 2; half++) {
                uint32_t bh[4][2], bl[4][2];
                #pragma unroll
                for (int nt = 0; nt < 4; nt++) {
                    int n = wn * 64 + half * 32 + nt * 8 + gid;
                    uint32_t o = (uint32_t)(n * PADK + kcol) * 2;
                    bh[nt][0] = lds32(Bhb + o);
                    bh[nt][1] = lds32(Bhb + o + 16);
                    bl[nt][0] = lds32(Blb + o);
                    bl[nt][1] = lds32(Blb + o + 16);
                }
                // term-major: consecutive MMAs hit different accumulators
                #pragma unroll
                for (int mt = 0; mt < 2; mt++)
                    #pragma unroll
                    for (int nt = 0; nt < 4; nt++)
                        mma16816(acc[mt][half*4 + nt], ah[mt], bh[nt]);
                #pragma unroll
                for (int mt = 0; mt < 2; mt++)
                    #pragma unroll
                    for (int nt = 0; nt < 4; nt++)
                        mma16816(acc[mt][half*4 + nt], ah[mt], bl[nt]);
                #pragma unroll
                for (int mt = 0; mt < 2; mt++)
                    #pragma unroll
                    for (int nt = 0; nt < 4; nt++)
                        mma16816(acc[mt][half*4 + nt], al[mt], bh[nt]);
            }
        }
        __syncthreads();
    }

    // ---- epilogue ----
    #pragma unroll
    for (int mt = 0; mt < 2; mt++) {
        int m_lo = row0 + wm * 32 + mt * 16 + gid;
        int m_hi = m_lo + 8;
        #pragma unroll
        for (int j = 0; j < 8; j++) {
            int nc = col0 + wn * 64 + (j >> 2) * 32 + (j & 3) * 8 + tig * 2;
            float b0 = bias[nc], b1 = bias[nc + 1];
            float* cc = acc[mt][j];
            float v0 = cc[0] + b0, v1 = cc[1] + b1;  // row m_lo
            float v2 = cc[2] + b0, v3 = cc[3] + b1;  // row m_hi
            if (mode == 0) {
                int which = (nc >= 2*DD) ? 2 : ((nc >= DD) ? 1 : 0);
                int rem = nc - which * DD;
                int h = rem >> 6, hs = rem & 63;
                int p0 = m_lo >> 10, n0 = m_lo & 1023;
                int p1 = m_hi >> 10, n1 = m_hi & 1023;
                int ph0 = p0 * HH + h, ph1 = p1 * HH + h;
                uint32_t whi, wlo;
                if (which == 2) {
                    size_t r0 = ((size_t)ph0 * HSZ + hs) * NN;
                    size_t r1 = ((size_t)ph1 * HSZ + hs) * NN;
                    split2(v0, v1, whi, wlo);
                    gVth[r0 + n0] = __ushort_as_bfloat16((unsigned short)(whi & 0xffff));
                    gVth[r0 + NN + n0] = __ushort_as_bfloat16((unsigned short)(whi >> 16));
                    gVtl[r0 + n0] = __ushort_as_bfloat16((unsigned short)(wlo & 0xffff));
                    gVtl[r0 + NN + n0] = __ushort_as_bfloat16((unsigned short)(wlo >> 16));
                    split2(v2, v3, whi, wlo);
                    gVth[r1 + n1] = __ushort_as_bfloat16((unsigned short)(whi & 0xffff));
                    gVth[r1 + NN + n1] = __ushort_as_bfloat16((unsigned short)(whi >> 16));
                    gVtl[r1 + n1] = __ushort_as_bfloat16((unsigned short)(wlo & 0xffff));
                    gVtl[r1 + NN + n1] = __ushort_as_bfloat16((unsigned short)(wlo >> 16));
                } else {
                    __nv_bfloat16* dh = which ? gKh : gQh;
                    __nv_bfloat16* dl = which ? gKl : gQl;
                    size_t o0 = (((size_t)ph0 << 10) + n0) * HSZ + hs;
                    size_t o1 = (((size_t)ph1 << 10) + n1) * HSZ + hs;
                    split2(v0, v1, whi, wlo);
                    *(uint32_t*)&dh[o0] = whi; *(uint32_t*)&dl[o0] = wlo;
                    split2(v2, v3, whi, wlo);
                    *(uint32_t*)&dh[o1] = whi; *(uint32_t*)&dl[o1] = wlo;
                }
            } else {
                *(float2*)&out[(size_t)m_lo * DD + nc] = make_float2(v0, v1);
                *(float2*)&out[(size_t)m_hi * DD + nc] = make_float2(v2, v3);
            }
        }
    }
}

// ================= post-softmax mask term =================
__global__ void maskv_kernel(const float* __restrict__ mask) {
    int ph = blockIdx.x;
    int p = ph / HH;
    int w = threadIdx.x >> 5, lane = threadIdx.x & 31;
    const float* mp = mask + (size_t)p * NN;
    #pragma unroll
    for (int i = 0; i < 8; i++) {
        int hs = w * 8 + i;
        const __nv_bfloat16* vh = gVth + ((size_t)ph * HSZ + hs) * NN;
        const __nv_bfloat16* vl = gVtl + ((size_t)ph * HSZ + hs) * NN;
        float acc = 0.f;
        for (int k = lane; k < NN; k += 32)
            acc += mp[k] * (__bfloat162float(vh[k]) + __bfloat162float(vl[k]));
        #pragma unroll
        for (int s = 16; s > 0; s >>= 1) acc += __shfl_xor_sync(0xffffffffu, acc, s);
        if (lane == 0) gMV[ph * HSZ + hs] = acc;
    }
}

// ================= flash attention via mma.sync (bf16x3) =================
// CTA = (p, h, 128 q-rows), 256 threads = 8 warps x 16 q-rows.
// K-block 64, double buffered, 2 CTAs/SM. Term-major MMA issue in 4-acc groups.
#define AKS 72
#define KTILE_B (64*AKS*2)          // 9216 B
#define ABUF_B (4*KTILE_B)          // 36864 B
#define ATTN_SMEM (2*ABUF_B)        // 73728 B

__global__ __launch_bounds__(256, 2) void attn_mma() {
    extern __shared__ __align__(16) char smem[];
    uint32_t sb = smem_u32(smem);
    int tid = threadIdx.x, wid = tid >> 5, lane = tid & 31;
    int gid = lane >> 2, tig = lane & 3;
    int qb = blockIdx.x, h = blockIdx.y, p = blockIdx.z;
    int ph = p * HH + h;
    int q0 = qb * 128 + wid * 16;    // warp's first q row

    // ---- preload Q fragments (hi/lo), warp rows q0 + {gid, gid+8}
    uint32_t qh[4][4], ql[4][4];
    {
        const __nv_bfloat16* base_h = gQh + ((size_t)ph * NN + q0) * HSZ;
        const __nv_bfloat16* base_l = gQl + ((size_t)ph * NN + q0) * HSZ;
        #pragma unroll
        for (int kk = 0; kk < 4; kk++) {
            int c = kk * 16 + tig * 2;
            qh[kk][0] = *(const uint32_t*)(base_h + (size_t)gid * HSZ + c);
            qh[kk][1] = *(const uint32_t*)(base_h + (size_t)(gid+8) * HSZ + c);
            qh[kk][2] = *(const uint32_t*)(base_h + (size_t)gid * HSZ + c + 8);
            qh[kk][3] = *(const uint32_t*)(base_h + (size_t)(gid+8) * HSZ + c + 8);
            ql[kk][0] = *(const uint32_t*)(base_l + (size_t)gid * HSZ + c);
            ql[kk][1] = *(const uint32_t*)(base_l + (size_t)(gid+8) * HSZ + c);
            ql[kk][2] = *(const uint32_t*)(base_l + (size_t)gid * HSZ + c + 8);
            ql[kk][3] = *(const uint32_t*)(base_l + (size_t)(gid+8) * HSZ + c + 8);
        }
    }

    float oacc[8][4];
    #pragma unroll
    for (int i = 0; i < 8; i++)
        #pragma unroll
        for (int j = 0; j < 4; j++) oacc[i][j] = 0.f;
    float m0 = -1e30f, m1 = -1e30f, l0 = 0.f, l1 = 0.f;

    const __nv_bfloat16* Kh_g = gKh + (size_t)ph * NN * HSZ;
    const __nv_bfloat16* Kl_g = gKl + (size_t)ph * NN * HSZ;
    const __nv_bfloat16* Vh_g = gVth + (size_t)ph * HSZ * NN;
    const __nv_bfloat16* Vl_g = gVtl + (size_t)ph * HSZ * NN;

    auto fill = [&](int s, int kb) {
        uint32_t base = sb + s * ABUF_B;
        #pragma unroll
        for (int j = 0; j < 2; j++) {
            int e = j * 256 + tid;
            int r = e >> 3, ch = e & 7;
            uint32_t d = base + (uint32_t)(r * AKS + ch * 8) * 2;
            const __nv_bfloat16* gh = Kh_g + (size_t)(kb*64 + r) * HSZ + ch * 8;
            const __nv_bfloat16* gl = Kl_g + (size_t)(kb*64 + r) * HSZ + ch * 8;
            CP16(d, gh);
            CP16(d + KTILE_B, gl);
        }
        #pragma unroll
        for (int j = 0; j < 2; j++) {
            int e = j * 256 + tid;
            int r = e >> 3, ch = e & 7;
            uint32_t d = base + 2*KTILE_B + (uint32_t)(r * AKS + ch * 8) * 2;
            const __nv_bfloat16* gh = Vh_g + (size_t)r * NN + kb*64 + ch * 8;
            const __nv_bfloat16* gl = Vl_g + (size_t)r * NN + kb*64 + ch * 8;
            CP16(d, gh);
            CP16(d + KTILE_B, gl);
        }
        CP_COMMIT();
    };

    fill(0, 0);
    for (int kb = 0; kb < 16; kb++) {
        if (kb < 15) fill((kb + 1) & 1, kb + 1);
        if (kb < 15) CP_WAIT1(); else CP_WAIT0();
        __syncthreads();

        uint32_t base = sb + (kb & 1) * ABUF_B;
        uint32_t Khb = base, Klb = base + KTILE_B;
        uint32_t Vhb = base + 2*KTILE_B, Vlb = base + 3*KTILE_B;

        // ---- S = Q K^T (16 x 64 per warp), 3-term hi/lo, kk-outer term-major
        float sacc[8][4];
        #pragma unroll
        for (int nt = 0; nt < 8; nt++)
            #pragma unroll
            for (int j = 0; j < 4; j++) sacc[nt][j] = 0.f;
        #pragma unroll
        for (int kk = 0; kk < 4; kk++) {
            uint32_t co = (uint32_t)(kk*16 + tig*2) * 2;
            #pragma unroll
            for (int g = 0; g < 2; g++) {
                uint32_t bh[4][2], bl[4][2];
                #pragma unroll
                for (int n4 = 0; n4 < 4; n4++) {
                    uint32_t ro = (uint32_t)(((g*4 + n4)*8 + gid) * AKS) * 2;
                    bh[n4][0] = lds32(Khb + ro + co);
                    bh[n4][1] = lds32(Khb + ro + co + 16);
                    bl[n4][0] = lds32(Klb + ro + co);
                    bl[n4][1] = lds32(Klb + ro + co + 16);
                }
                #pragma unroll
                for (int n4 = 0; n4 < 4; n4++) mma16816(sacc[g*4+n4], qh[kk], bh[n4]);
                #pragma unroll
                for (int n4 = 0; n4 < 4; n4++) mma16816(sacc[g*4+n4], qh[kk], bl[n4]);
                #pragma unroll
                for (int n4 = 0; n4 < 4; n4++) mma16816(sacc[g*4+n4], ql[kk], bh[n4]);
            }
        }

        // ---- online softmax (scale x8 folded into exp2 constant)
        float mx0 = -1e30f, mx1 = -1e30f;
        #pragma unroll
        for (int nt = 0; nt < 8; nt++) {
            mx0 = fmaxf(mx0, fmaxf(sacc[nt][0], sacc[nt][1]));
            mx1 = fmaxf(mx1, fmaxf(sacc[nt][2], sacc[nt][3]));
        }
        mx0 = fmaxf(mx0, __shfl_xor_sync(0xffffffffu, mx0, 1));
        mx0 = fmaxf(mx0, __shfl_xor_sync(0xffffffffu, mx0, 2));
        mx1 = fmaxf(mx1, __shfl_xor_sync(0xffffffffu, mx1, 1));
        mx1 = fmaxf(mx1, __shfl_xor_sync(0xffffffffu, mx1, 2));
        float nm0 = fmaxf(m0, mx0), nm1 = fmaxf(m1, mx1);
        float corr0 = exp2f((m0 - nm0) * SCLOG2);
        float corr1 = exp2f((m1 - nm1) * SCLOG2);
        m0 = nm0; m1 = nm1;
        float rs0 = 0.f, rs1 = 0.f;
        #pragma unroll
        for (int nt = 0; nt < 8; nt++) {
            sacc[nt][0] = exp2f((sacc[nt][0] - nm0) * SCLOG2);
            sacc[nt][1] = exp2f((sacc[nt][1] - nm0) * SCLOG2);
            sacc[nt][2] = exp2f((sacc[nt][2] - nm1) * SCLOG2);
            sacc[nt][3] = exp2f((sacc[nt][3] - nm1) * SCLOG2);
            rs0 += sacc[nt][0] + sacc[nt][1];
            rs1 += sacc[nt][2] + sacc[nt][3];
        }
        rs0 += __shfl_xor_sync(0xffffffffu, rs0, 1);
        rs0 += __shfl_xor_sync(0xffffffffu, rs0, 2);
        rs1 += __shfl_xor_sync(0xffffffffu, rs1, 1);
        rs1 += __shfl_xor_sync(0xffffffffu, rs1, 2);
        l0 = l0 * corr0 + rs0;
        l1 = l1 * corr1 + rs1;
        #pragma unroll
        for (int nt = 0; nt < 8; nt++) {
            oacc[nt][0] *= corr0; oacc[nt][1] *= corr0;
            oacc[nt][2] *= corr1; oacc[nt][3] *= corr1;
        }

        // ---- O += P V, term-major in 4-acc groups
        #pragma unroll
        for (int kblk = 0; kblk < 4; kblk++) {
            uint32_t ah[4], al[4];
            split2(sacc[2*kblk][0],   sacc[2*kblk][1],   ah[0], al[0]);
            split2(sacc[2*kblk][2],   sacc[2*kblk][3],   ah[1], al[1]);
            split2(sacc[2*kblk+1][0], sacc[2*kblk+1][1], ah[2], al[2]);
            split2(sacc[2*kblk+1][2], sacc[2*kblk+1][3], ah[3], al[3]);
            uint32_t co = (uint32_t)(kblk*16 + tig*2) * 2;
            #pragma unroll
            for (int g = 0; g < 2; g++) {
                uint32_t bh[4][2], bl[4][2];
                #pragma unroll
                for (int n4 = 0; n4 < 4; n4++) {
                    uint32_t ro = (uint32_t)(((g*4 + n4)*8 + gid) * AKS) * 2;
                    bh[n4][0] = lds32(Vhb + ro + co);
                    bh[n4][1] = lds32(Vhb + ro + co + 16);
                    bl[n4][0] = lds32(Vlb + ro + co);
                    bl[n4][1] = lds32(Vlb + ro + co + 16);
                }
                #pragma unroll
                for (int n4 = 0; n4 < 4; n4++) mma16816(oacc[g*4+n4], ah, bh[n4]);
                #pragma unroll
                for (int n4 = 0; n4 < 4; n4++) mma16816(oacc[g*4+n4], ah, bl[n4]);
                #pragma unroll
                for (int n4 = 0; n4 < 4; n4++) mma16816(oacc[g*4+n4], al, bh[n4]);
            }
        }
        __syncthreads();
    }

    // ---- epilogue: ctx = O/l + maskV, stored bf16 hi/lo
    float inv0 = 1.0f / l0, inv1 = 1.0f / l1;
    int q_lo = q0 + gid;
    int q_hi = q_lo + 8;
    #pragma unroll
    for (int nt = 0; nt < 8; nt++) {
        int hs = nt*8 + tig*2;
        float mv0 = gMV[ph*HSZ + hs], mv1 = gMV[ph*HSZ + hs + 1];
        float v0 = oacc[nt][0]*inv0 + mv0, v1 = oacc[nt][1]*inv0 + mv1;
        float v2 = oacc[nt][2]*inv1 + mv0, v3 = oacc[nt][3]*inv1 + mv1;
        size_t o0 = ((size_t)p*NN + q_lo) * DD + h*HSZ + hs;
        size_t o1 = ((size_t)p*NN + q_hi) * DD + h*HSZ + hs;
        uint32_t whi, wlo;
        split2(v0, v1, whi, wlo);
        *(uint32_t*)&gCh[o0] = whi; *(uint32_t*)&gCl[o0] = wlo;
        split2(v2, v3, whi, wlo);
        *(uint32_t*)&gCh[o1] = whi; *(uint32_t*)&gCl[o1] = wlo;
    }
}

extern "C" void kernel_launch(void* const* d_in, const int* in_sizes, int n_in,
                              void* d_out, int out_size) {
    const float* X      = (const float*)d_in[0];
    const float* mask   = (const float*)d_in[1];
    const float* qkv_w  = (const float*)d_in[2];
    const float* qkv_b  = (const float*)d_in[3];
    const float* proj_w = (const float*)d_in[4];
    const float* proj_b = (const float*)d_in[5];
    float* out = (float*)d_out;

    cudaFuncSetAttribute(gemm_mma, cudaFuncAttributeMaxDynamicSharedMemorySize, GEMM_SMEM);
    cudaFuncSetAttribute(attn_mma, cudaFuncAttributeMaxDynamicSharedMemorySize, ATTN_SMEM);

    __nv_bfloat16 *xhi, *xlo, *wqh, *wql, *wph, *wpl;
    cudaGetSymbolAddress((void**)&xhi, gXhi);
    cudaGetSymbolAddress((void**)&xlo, gXlo);
    cudaGetSymbolAddress((void**)&wqh, gWqh);
    cudaGetSymbolAddress((void**)&wql, gWql);
    cudaGetSymbolAddress((void**)&wph, gWph);
    cudaGetSymbolAddress((void**)&wpl, gWpl);

    split_kernel<<<(PP*NN*DD/4 + 255)/256, 256>>>(X, xhi, xlo, PP*NN*DD/4);
    tsplit_kernel<<<dim3(3*DD/32, DD/32), dim3(32,8)>>>(qkv_w, wqh, wql, DD, 3*DD);
    tsplit_kernel<<<dim3(DD/32, DD/32), dim3(32,8)>>>(proj_w, wph, wpl, DD, DD);
    gemm_mma<<<dim3(3*DD/128, PP*NN/128), 256, GEMM_SMEM>>>(0, qkv_b, nullptr);
    maskv_kernel<<<PP*HH, 256>>>(mask);
    attn_mma<<<dim3(NN/128, HH, PP), 256, ATTN_SMEM>>>();
    gemm_mma<<<dim3(DD/128, PP*NN/128), 256, GEMM_SMEM>>>(1, proj_b, out);
}

// round 15
// speedup vs baseline: 1.2054x; 1.1338x over previous
#include <cuda_runtime.h>
#include <cuda_bf16.h>
#include <cuda_fp16.h>
#include <cstdint>

#define PP 8
#define NN 1024
#define DD 768
#define HH 12
#define HSZ 64
#define SCLOG2 11.5423594967f   // 8 * log2(e)

// ---- scratch (static) ----
__device__ float gMV[PP*HH*HSZ];
__device__ __nv_bfloat16 gXhi[PP*NN*DD];
__device__ __nv_bfloat16 gXlo[PP*NN*DD];
__device__ __nv_bfloat16 gWqh[3*DD*DD];
__device__ __nv_bfloat16 gWql[3*DD*DD];
__device__ __half gWp[DD*DD];          // proj_w transposed, single fp16
__device__ __half gCh[PP*NN*DD];       // ctx fp16 hi/lo
__device__ __half gCl[PP*NN*DD];
// attention: Q,K bf16 hi/lo [ph][n][hs]; V transposed single fp16 [ph][hs][n]
__device__ __nv_bfloat16 gQh[PP*HH*NN*HSZ];
__device__ __nv_bfloat16 gQl[PP*HH*NN*HSZ];
__device__ __nv_bfloat16 gKh[PP*HH*NN*HSZ];
__device__ __nv_bfloat16 gKl[PP*HH*NN*HSZ];
__device__ __half gVt[PP*HH*NN*HSZ];

// ================= helpers =================
__device__ __forceinline__ uint32_t smem_u32(const void* p) {
    uint32_t a;
    asm("{ .reg .u64 t; cvta.to.shared.u64 t, %1; cvt.u32.u64 %0, t; }" : "=r"(a) : "l"(p));
    return a;
}
__device__ __forceinline__ uint32_t lds32(uint32_t a) {
    uint32_t v;
    asm volatile("ld.shared.b32 %0, [%1];" : "=r"(v) : "r"(a));
    return v;
}
#define CP16(saddr, gptr) \
    asm volatile("cp.async.cg.shared.global [%0], [%1], 16;" :: "r"(saddr), "l"(gptr))
#define CP_COMMIT() asm volatile("cp.async.commit_group;" ::: "memory")
#define CP_WAIT1()  asm volatile("cp.async.wait_group 1;" ::: "memory")
#define CP_WAIT0()  asm volatile("cp.async.wait_group 0;" ::: "memory")

__device__ __forceinline__ void mma_bf(float* c, const uint32_t* a, const uint32_t* b) {
    asm volatile("mma.sync.aligned.m16n8k16.row.col.f32.bf16.bf16.f32 "
                 "{%0,%1,%2,%3}, {%4,%5,%6,%7}, {%8,%9}, {%0,%1,%2,%3};"
                 : "+f"(c[0]), "+f"(c[1]), "+f"(c[2]), "+f"(c[3])
                 : "r"(a[0]), "r"(a[1]), "r"(a[2]), "r"(a[3]), "r"(b[0]), "r"(b[1]));
}
__device__ __forceinline__ void mma_hf(float* c, const uint32_t* a, const uint32_t* b) {
    asm volatile("mma.sync.aligned.m16n8k16.row.col.f32.f16.f16.f32 "
                 "{%0,%1,%2,%3}, {%4,%5,%6,%7}, {%8,%9}, {%0,%1,%2,%3};"
                 : "+f"(c[0]), "+f"(c[1]), "+f"(c[2]), "+f"(c[3])
                 : "r"(a[0]), "r"(a[1]), "r"(a[2]), "r"(a[3]), "r"(b[0]), "r"(b[1]));
}
// bf16 pack / split
__device__ __forceinline__ uint32_t pack2(float v0, float v1) {
    uint32_t r;
    asm("cvt.rn.bf16x2.f32 %0, %1, %2;" : "=r"(r) : "f"(v1), "f"(v0));
    return r;
}
__device__ __forceinline__ void split2(float v0, float v1, uint32_t& phi, uint32_t& plo) {
    phi = pack2(v0, v1);
    float h0 = __uint_as_float(phi << 16);
    float h1 = __uint_as_float(phi & 0xffff0000u);
    plo = pack2(v0 - h0, v1 - h1);
}
// fp16 pack / split
__device__ __forceinline__ uint32_t pack2h(float v0, float v1) {
    uint32_t r;
    asm("cvt.rn.f16x2.f32 %0, %1, %2;" : "=r"(r) : "f"(v1), "f"(v0));
    return r;
}
__device__ __forceinline__ void split2h(float v0, float v1, uint32_t& phi, uint32_t& plo) {
    phi = pack2h(v0, v1);
    float h0 = __half2float(__ushort_as_half((unsigned short)(phi & 0xffff)));
    float h1 = __half2float(__ushort_as_half((unsigned short)(phi >> 16)));
    plo = pack2h(v0 - h0, v1 - h1);
}

// ================= split / transpose =================
__global__ void split_kernel(const float* __restrict__ src,
                             __nv_bfloat16* __restrict__ hi,
                             __nv_bfloat16* __restrict__ lo, int n4) {
    int i = blockIdx.x * blockDim.x + threadIdx.x;
    if (i >= n4) return;
    float4 v = ((const float4*)src)[i];
    uint32_t h[2], l[2];
    split2(v.x, v.y, h[0], l[0]);
    split2(v.z, v.w, h[1], l[1]);
    ((uint2*)hi)[i] = make_uint2(h[0], h[1]);
    ((uint2*)lo)[i] = make_uint2(l[0], l[1]);
}

// W[K][N] -> T[N][K], bf16 hi/lo
__global__ void tsplit_kernel(const float* __restrict__ W,
                              __nv_bfloat16* __restrict__ Th,
                              __nv_bfloat16* __restrict__ Tl, int K, int N) {
    __shared__ float t[32][33];
    int k0 = blockIdx.y * 32, n0 = blockIdx.x * 32;
    int tx = threadIdx.x, ty = threadIdx.y;
    #pragma unroll
    for (int i = 0; i < 4; i++)
        t[ty + 8*i][tx] = W[(size_t)(k0 + ty + 8*i) * N + n0 + tx];
    __syncthreads();
    #pragma unroll
    for (int i = 0; i < 4; i++) {
        float x = t[tx][ty + 8*i];
        __nv_bfloat16 h = __float2bfloat16_rn(x);
        __nv_bfloat16 l = __float2bfloat16_rn(x - __bfloat162float(h));
        size_t o = (size_t)(n0 + ty + 8*i) * K + k0 + tx;
        Th[o] = h; Tl[o] = l;
    }
}

// W[K][N] -> T[N][K], single fp16
__global__ void ttrans_kernel(const float* __restrict__ W,
                              __half* __restrict__ Th, int K, int N) {
    __shared__ float t[32][33];
    int k0 = blockIdx.y * 32, n0 = blockIdx.x * 32;
    int tx = threadIdx.x, ty = threadIdx.y;
    #pragma unroll
    for (int i = 0; i < 4; i++)
        t[ty + 8*i][tx] = W[(size_t)(k0 + ty + 8*i) * N + n0 + tx];
    __syncthreads();
    #pragma unroll
    for (int i = 0; i < 4; i++) {
        size_t o = (size_t)(n0 + ty + 8*i) * K + k0 + tx;
        Th[o] = __float2half_rn(t[tx][ty + 8*i]);
    }
}

// ================= QKV GEMM: bf16x3 (accuracy-critical) =================
#define PADK 40
#define TILE_E (128*PADK)
#define QBUF_BYTES (4*TILE_E*2)       // 40960 B per buffer
#define QKV_SMEM (2*QBUF_BYTES)       // 81920 B

__global__ __launch_bounds__(256, 2) void qkv_gemm(const float* __restrict__ bias) {
    extern __shared__ __align__(16) char smem[];
    uint32_t sb = smem_u32(smem);
    int tid = threadIdx.x, wid = tid >> 5, lane = tid & 31;
    int wm = wid & 3, wn = wid >> 2;
    int row0 = blockIdx.y * 128, col0 = blockIdx.x * 128;
    int gid = lane >> 2, tig = lane & 3;

    const __nv_bfloat16* srcs[4] = {gXhi, gXlo, gWqh, gWql};

    float acc[2][8][4];
    #pragma unroll
    for (int i = 0; i < 2; i++)
        #pragma unroll
        for (int j = 0; j < 8; j++)
            #pragma unroll
            for (int q = 0; q < 4; q++) acc[i][j][q] = 0.f;

    auto fill = [&](int s, int c) {
        int k0 = c * 32;
        uint32_t sbase = sb + s * QBUF_BYTES;
        #pragma unroll
        for (int t = 0; t < 4; t++) {
            const __nv_bfloat16* src = srcs[t];
            int rbase = (t < 2) ? row0 : col0;
            #pragma unroll
            for (int j = 0; j < 2; j++) {
                int e = j * 256 + tid;
                int r = e >> 2, v = e & 3;
                uint32_t daddr = sbase + (uint32_t)(t * TILE_E + r * PADK + v * 8) * 2;
                CP16(daddr, src + (size_t)(rbase + r) * DD + k0 + v * 8);
            }
        }
        CP_COMMIT();
    };

    fill(0, 0);
    for (int c = 0; c < 24; c++) {
        if (c < 23) fill((c + 1) & 1, c + 1);
        if (c < 23) CP_WAIT1(); else CP_WAIT0();
        __syncthreads();

        uint32_t base = sb + (c & 1) * QBUF_BYTES;
        uint32_t Ahb = base, Alb = base + TILE_E*2;
        uint32_t Bhb = base + 2*TILE_E*2, Blb = Bhb + TILE_E*2;

        #pragma unroll
        for (int ks = 0; ks < 2; ks++) {
            int kcol = ks * 16 + tig * 2;
            uint32_t ah[2][4], al[2][4];
            #pragma unroll
            for (int mt = 0; mt < 2; mt++) {
                int r = wm * 32 + mt * 16 + gid;
                uint32_t o = (uint32_t)(r * PADK + kcol) * 2;
                ah[mt][0] = lds32(Ahb + o);
                ah[mt][1] = lds32(Ahb + o + 8*PADK*2);
                ah[mt][2] = lds32(Ahb + o + 16);
                ah[mt][3] = lds32(Ahb + o + 8*PADK*2 + 16);
                al[mt][0] = lds32(Alb + o);
                al[mt][1] = lds32(Alb + o + 8*PADK*2);
                al[mt][2] = lds32(Alb + o + 16);
                al[mt][3] = lds32(Alb + o + 8*PADK*2 + 16);
            }
            #pragma unroll
            for (int half = 0; half < 2; half++) {
                uint32_t bh[4][2], bl[4][2];
                #pragma unroll
                for (int nt = 0; nt < 4; nt++) {
                    int n = wn * 64 + half * 32 + nt * 8 + gid;
                    uint32_t o = (uint32_t)(n * PADK + kcol) * 2;
                    bh[nt][0] = lds32(Bhb + o);
                    bh[nt][1] = lds32(Bhb + o + 16);
                    bl[nt][0] = lds32(Blb + o);
                    bl[nt][1] = lds32(Blb + o + 16);
                }
                #pragma unroll
                for (int mt = 0; mt < 2; mt++)
                    #pragma unroll
                    for (int nt = 0; nt < 4; nt++)
                        mma_bf(acc[mt][half*4 + nt], ah[mt], bh[nt]);
                #pragma unroll
                for (int mt = 0; mt < 2; mt++)
                    #pragma unroll
                    for (int nt = 0; nt < 4; nt++)
                        mma_bf(acc[mt][half*4 + nt], ah[mt], bl[nt]);
                #pragma unroll
                for (int mt = 0; mt < 2; mt++)
                    #pragma unroll
                    for (int nt = 0; nt < 4; nt++)
                        mma_bf(acc[mt][half*4 + nt], al[mt], bh[nt]);
            }
        }
        __syncthreads();
    }

    // ---- epilogue: Q,K bf16 hi/lo; V transposed single fp16 ----
    #pragma unroll
    for (int mt = 0; mt < 2; mt++) {
        int m_lo = row0 + wm * 32 + mt * 16 + gid;
        int m_hi = m_lo + 8;
        #pragma unroll
        for (int j = 0; j < 8; j++) {
            int nc = col0 + wn * 64 + (j >> 2) * 32 + (j & 3) * 8 + tig * 2;
            float b0 = bias[nc], b1 = bias[nc + 1];
            float* cc = acc[mt][j];
            float v0 = cc[0] + b0, v1 = cc[1] + b1;
            float v2 = cc[2] + b0, v3 = cc[3] + b1;
            int which = (nc >= 2*DD) ? 2 : ((nc >= DD) ? 1 : 0);
            int rem = nc - which * DD;
            int h = rem >> 6, hs = rem & 63;
            int p0 = m_lo >> 10, n0 = m_lo & 1023;
            int p1 = m_hi >> 10, n1 = m_hi & 1023;
            int ph0 = p0 * HH + h, ph1 = p1 * HH + h;
            if (which == 2) {
                size_t r0 = ((size_t)ph0 * HSZ + hs) * NN;
                size_t r1 = ((size_t)ph1 * HSZ + hs) * NN;
                gVt[r0 + n0]      = __float2half_rn(v0);
                gVt[r0 + NN + n0] = __float2half_rn(v1);
                gVt[r1 + n1]      = __float2half_rn(v2);
                gVt[r1 + NN + n1] = __float2half_rn(v3);
            } else {
                __nv_bfloat16* dh = which ? gKh : gQh;
                __nv_bfloat16* dl = which ? gKl : gQl;
                size_t o0 = (((size_t)ph0 << 10) + n0) * HSZ + hs;
                size_t o1 = (((size_t)ph1 << 10) + n1) * HSZ + hs;
                uint32_t whi, wlo;
                split2(v0, v1, whi, wlo);
                *(uint32_t*)&dh[o0] = whi; *(uint32_t*)&dl[o0] = wlo;
                split2(v2, v3, whi, wlo);
                *(uint32_t*)&dh[o1] = whi; *(uint32_t*)&dl[o1] = wlo;
            }
        }
    }
}

// ================= proj GEMM: fp16 2-term =================
#define PBUF_BYTES (3*TILE_E*2)       // 30720 B per buffer
#define PROJ_SMEM (2*PBUF_BYTES)      // 61440 B

__global__ __launch_bounds__(256, 2) void proj_gemm(const float* __restrict__ bias,
                                                    float* __restrict__ out) {
    extern __shared__ __align__(16) char smem[];
    uint32_t sb = smem_u32(smem);
    int tid = threadIdx.x, wid = tid >> 5, lane = tid & 31;
    int wm = wid & 3, wn = wid >> 2;
    int row0 = blockIdx.y * 128, col0 = blockIdx.x * 128;
    int gid = lane >> 2, tig = lane & 3;

    const __half* srcs[3] = {gCh, gCl, gWp};

    float acc[2][8][4];
    #pragma unroll
    for (int i = 0; i < 2; i++)
        #pragma unroll
        for (int j = 0; j < 8; j++)
            #pragma unroll
            for (int q = 0; q < 4; q++) acc[i][j][q] = 0.f;

    auto fill = [&](int s, int c) {
        int k0 = c * 32;
        uint32_t sbase = sb + s * PBUF_BYTES;
        #pragma unroll
        for (int t = 0; t < 3; t++) {
            const __half* src = srcs[t];
            int rbase = (t < 2) ? row0 : col0;
            #pragma unroll
            for (int j = 0; j < 2; j++) {
                int e = j * 256 + tid;
                int r = e >> 2, v = e & 3;
                uint32_t daddr = sbase + (uint32_t)(t * TILE_E + r * PADK + v * 8) * 2;
                CP16(daddr, src + (size_t)(rbase + r) * DD + k0 + v * 8);
            }
        }
        CP_COMMIT();
    };

    fill(0, 0);
    for (int c = 0; c < 24; c++) {
        if (c < 23) fill((c + 1) & 1, c + 1);
        if (c < 23) CP_WAIT1(); else CP_WAIT0();
        __syncthreads();

        uint32_t base = sb + (c & 1) * PBUF_BYTES;
        uint32_t Ahb = base, Alb = base + TILE_E*2, Bb = base + 2*TILE_E*2;

        #pragma unroll
        for (int ks = 0; ks < 2; ks++) {
            int kcol = ks * 16 + tig * 2;
            uint32_t ah[2][4], al[2][4];
            #pragma unroll
            for (int mt = 0; mt < 2; mt++) {
                int r = wm * 32 + mt * 16 + gid;
                uint32_t o = (uint32_t)(r * PADK + kcol) * 2;
                ah[mt][0] = lds32(Ahb + o);
                ah[mt][1] = lds32(Ahb + o + 8*PADK*2);
                ah[mt][2] = lds32(Ahb + o + 16);
                ah[mt][3] = lds32(Ahb + o + 8*PADK*2 + 16);
                al[mt][0] = lds32(Alb + o);
                al[mt][1] = lds32(Alb + o + 8*PADK*2);
                al[mt][2] = lds32(Alb + o + 16);
                al[mt][3] = lds32(Alb + o + 8*PADK*2 + 16);
            }
            #pragma unroll
            for (int half = 0; half < 2; half++) {
                uint32_t bb[4][2];
                #pragma unroll
                for (int nt = 0; nt < 4; nt++) {
                    int n = wn * 64 + half * 32 + nt * 8 + gid;
                    uint32_t o = (uint32_t)(n * PADK + kcol) * 2;
                    bb[nt][0] = lds32(Bb + o);
                    bb[nt][1] = lds32(Bb + o + 16);
                }
                #pragma unroll
                for (int mt = 0; mt < 2; mt++)
                    #pragma unroll
                    for (int nt = 0; nt < 4; nt++)
                        mma_hf(acc[mt][half*4 + nt], ah[mt], bb[nt]);
                #pragma unroll
                for (int mt = 0; mt < 2; mt++)
                    #pragma unroll
                    for (int nt = 0; nt < 4; nt++)
                        mma_hf(acc[mt][half*4 + nt], al[mt], bb[nt]);
            }
        }
        __syncthreads();
    }

    #pragma unroll
    for (int mt = 0; mt < 2; mt++) {
        int m_lo = row0 + wm * 32 + mt * 16 + gid;
        int m_hi = m_lo + 8;
        #pragma unroll
        for (int j = 0; j < 8; j++) {
            int nc = col0 + wn * 64 + (j >> 2) * 32 + (j & 3) * 8 + tig * 2;
            float b0 = bias[nc], b1 = bias[nc + 1];
            float* cc = acc[mt][j];
            *(float2*)&out[(size_t)m_lo * DD + nc] = make_float2(cc[0] + b0, cc[1] + b1);
            *(float2*)&out[(size_t)m_hi * DD + nc] = make_float2(cc[2] + b0, cc[3] + b1);
        }
    }
}

// ================= post-softmax mask term =================
__global__ void maskv_kernel(const float* __restrict__ mask) {
    int ph = blockIdx.x;
    int p = ph / HH;
    int w = threadIdx.x >> 5, lane = threadIdx.x & 31;
    const float* mp = mask + (size_t)p * NN;
    #pragma unroll
    for (int i = 0; i < 8; i++) {
        int hs = w * 8 + i;
        const __half* vh = gVt + ((size_t)ph * HSZ + hs) * NN;
        float acc = 0.f;
        for (int k = lane; k < NN; k += 32)
            acc += mp[k] * __half2float(vh[k]);
        #pragma unroll
        for (int s = 16; s > 0; s >>= 1) acc += __shfl_xor_sync(0xffffffffu, acc, s);
        if (lane == 0) gMV[ph * HSZ + hs] = acc;
    }
}

// ================= flash attention: S bf16x3, PV fp16x2 =================
// CTA = (p, h, 128 q-rows), 256 threads = 8 warps x 16 q-rows.
// K-block 64, double buffered, 2 CTAs/SM.
// smem per buffer: Kh[64][72], Kl[64][72] bf16, Vt[64][72] fp16.
#define AKS 72
#define KTILE_B (64*AKS*2)          // 9216 B
#define ABUF_B (3*KTILE_B)          // 27648 B
#define ATTN_SMEM (2*ABUF_B)        // 55296 B

__global__ __launch_bounds__(256, 2) void attn_mma() {
    extern __shared__ __align__(16) char smem[];
    uint32_t sb = smem_u32(smem);
    int tid = threadIdx.x, wid = tid >> 5, lane = tid & 31;
    int gid = lane >> 2, tig = lane & 3;
    int qb = blockIdx.x, h = blockIdx.y, p = blockIdx.z;
    int ph = p * HH + h;
    int q0 = qb * 128 + wid * 16;

    // ---- preload Q fragments (bf16 hi/lo)
    uint32_t qh[4][4], ql[4][4];
    {
        const __nv_bfloat16* base_h = gQh + ((size_t)ph * NN + q0) * HSZ;
        const __nv_bfloat16* base_l = gQl + ((size_t)ph * NN + q0) * HSZ;
        #pragma unroll
        for (int kk = 0; kk < 4; kk++) {
            int c = kk * 16 + tig * 2;
            qh[kk][0] = *(const uint32_t*)(base_h + (size_t)gid * HSZ + c);
            qh[kk][1] = *(const uint32_t*)(base_h + (size_t)(gid+8) * HSZ + c);
            qh[kk][2] = *(const uint32_t*)(base_h + (size_t)gid * HSZ + c + 8);
            qh[kk][3] = *(const uint32_t*)(base_h + (size_t)(gid+8) * HSZ + c + 8);
            ql[kk][0] = *(const uint32_t*)(base_l + (size_t)gid * HSZ + c);
            ql[kk][1] = *(const uint32_t*)(base_l + (size_t)(gid+8) * HSZ + c);
            ql[kk][2] = *(const uint32_t*)(base_l + (size_t)gid * HSZ + c + 8);
            ql[kk][3] = *(const uint32_t*)(base_l + (size_t)(gid+8) * HSZ + c + 8);
        }
    }

    float oacc[8][4];
    #pragma unroll
    for (int i = 0; i < 8; i++)
        #pragma unroll
        for (int j = 0; j < 4; j++) oacc[i][j] = 0.f;
    float m0 = -1e30f, m1 = -1e30f, l0 = 0.f, l1 = 0.f;

    const __nv_bfloat16* Kh_g = gKh + (size_t)ph * NN * HSZ;
    const __nv_bfloat16* Kl_g = gKl + (size_t)ph * NN * HSZ;
    const __half* V_g = gVt + (size_t)ph * HSZ * NN;

    auto fill = [&](int s, int kb) {
        uint32_t base = sb + s * ABUF_B;
        // K tiles (bf16 hi/lo): 512 x 16B chunks each
        #pragma unroll
        for (int j = 0; j < 2; j++) {
            int e = j * 256 + tid;
            int r = e >> 3, ch = e & 7;
            uint32_t d = base + (uint32_t)(r * AKS + ch * 8) * 2;
            CP16(d, Kh_g + (size_t)(kb*64 + r) * HSZ + ch * 8);
            CP16(d + KTILE_B, Kl_g + (size_t)(kb*64 + r) * HSZ + ch * 8);
        }
        // Vt tile (fp16 single): 512 x 16B chunks
        #pragma unroll
        for (int j = 0; j < 2; j++) {
            int e = j * 256 + tid;
            int r = e >> 3, ch = e & 7;
            uint32_t d = base + 2*KTILE_B + (uint32_t)(r * AKS + ch * 8) * 2;
            CP16(d, V_g + (size_t)r * NN + kb*64 + ch * 8);
        }
        CP_COMMIT();
    };

    fill(0, 0);
    for (int kb = 0; kb < 16; kb++) {
        if (kb < 15) fill((kb + 1) & 1, kb + 1);
        if (kb < 15) CP_WAIT1(); else CP_WAIT0();
        __syncthreads();

        uint32_t base = sb + (kb & 1) * ABUF_B;
        uint32_t Khb = base, Klb = base + KTILE_B, Vb = base + 2*KTILE_B;

        // ---- S = Q K^T, bf16 3-term
        float sacc[8][4];
        #pragma unroll
        for (int nt = 0; nt < 8; nt++)
            #pragma unroll
            for (int j = 0; j < 4; j++) sacc[nt][j] = 0.f;
        #pragma unroll
        for (int kk = 0; kk < 4; kk++) {
            uint32_t co = (uint32_t)(kk*16 + tig*2) * 2;
            #pragma unroll
            for (int g = 0; g < 2; g++) {
                uint32_t bh[4][2], bl[4][2];
                #pragma unroll
                for (int n4 = 0; n4 < 4; n4++) {
                    uint32_t ro = (uint32_t)(((g*4 + n4)*8 + gid) * AKS) * 2;
                    bh[n4][0] = lds32(Khb + ro + co);
                    bh[n4][1] = lds32(Khb + ro + co + 16);
                    bl[n4][0] = lds32(Klb + ro + co);
                    bl[n4][1] = lds32(Klb + ro + co + 16);
                }
                #pragma unroll
                for (int n4 = 0; n4 < 4; n4++) mma_bf(sacc[g*4+n4], qh[kk], bh[n4]);
                #pragma unroll
                for (int n4 = 0; n4 < 4; n4++) mma_bf(sacc[g*4+n4], qh[kk], bl[n4]);
                #pragma unroll
                for (int n4 = 0; n4 < 4; n4++) mma_bf(sacc[g*4+n4], ql[kk], bh[n4]);
            }
        }

        // ---- online softmax
        float mx0 = -1e30f, mx1 = -1e30f;
        #pragma unroll
        for (int nt = 0; nt < 8; nt++) {
            mx0 = fmaxf(mx0, fmaxf(sacc[nt][0], sacc[nt][1]));
            mx1 = fmaxf(mx1, fmaxf(sacc[nt][2], sacc[nt][3]));
        }
        mx0 = fmaxf(mx0, __shfl_xor_sync(0xffffffffu, mx0, 1));
        mx0 = fmaxf(mx0, __shfl_xor_sync(0xffffffffu, mx0, 2));
        mx1 = fmaxf(mx1, __shfl_xor_sync(0xffffffffu, mx1, 1));
        mx1 = fmaxf(mx1, __shfl_xor_sync(0xffffffffu, mx1, 2));
        float nm0 = fmaxf(m0, mx0), nm1 = fmaxf(m1, mx1);
        float corr0 = exp2f((m0 - nm0) * SCLOG2);
        float corr1 = exp2f((m1 - nm1) * SCLOG2);
        m0 = nm0; m1 = nm1;
        float rs0 = 0.f, rs1 = 0.f;
        #pragma unroll
        for (int nt = 0; nt < 8; nt++) {
            sacc[nt][0] = exp2f((sacc[nt][0] - nm0) * SCLOG2);
            sacc[nt][1] = exp2f((sacc[nt][1] - nm0) * SCLOG2);
            sacc[nt][2] = exp2f((sacc[nt][2] - nm1) * SCLOG2);
            sacc[nt][3] = exp2f((sacc[nt][3] - nm1) * SCLOG2);
            rs0 += sacc[nt][0] + sacc[nt][1];
            rs1 += sacc[nt][2] + sacc[nt][3];
        }
        rs0 += __shfl_xor_sync(0xffffffffu, rs0, 1);
        rs0 += __shfl_xor_sync(0xffffffffu, rs0, 2);
        rs1 += __shfl_xor_sync(0xffffffffu, rs1, 1);
        rs1 += __shfl_xor_sync(0xffffffffu, rs1, 2);
        l0 = l0 * corr0 + rs0;
        l1 = l1 * corr1 + rs1;
        #pragma unroll
        for (int nt = 0; nt < 8; nt++) {
            oacc[nt][0] *= corr0; oacc[nt][1] *= corr0;
            oacc[nt][2] *= corr1; oacc[nt][3] *= corr1;
        }

        // ---- O += P V, fp16 2-term (P fp16 split, V fp16 single)
        #pragma unroll
        for (int kblk = 0; kblk < 4; kblk++) {
            uint32_t ah[4], al[4];
            split2h(sacc[2*kblk][0],   sacc[2*kblk][1],   ah[0], al[0]);
            split2h(sacc[2*kblk][2],   sacc[2*kblk][3],   ah[1], al[1]);
            split2h(sacc[2*kblk+1][0], sacc[2*kblk+1][1], ah[2], al[2]);
            split2h(sacc[2*kblk+1][2], sacc[2*kblk+1][3], ah[3], al[3]);
            uint32_t co = (uint32_t)(kblk*16 + tig*2) * 2;
            #pragma unroll
            for (int g = 0; g < 2; g++) {
                uint32_t bb[4][2];
                #pragma unroll
                for (int n4 = 0; n4 < 4; n4++) {
                    uint32_t ro = (uint32_t)(((g*4 + n4)*8 + gid) * AKS) * 2;
                    bb[n4][0] = lds32(Vb + ro + co);
                    bb[n4][1] = lds32(Vb + ro + co + 16);
                }
                #pragma unroll
                for (int n4 = 0; n4 < 4; n4++) mma_hf(oacc[g*4+n4], ah, bb[n4]);
                #pragma unroll
                for (int n4 = 0; n4 < 4; n4++) mma_hf(oacc[g*4+n4], al, bb[n4]);
            }
        }
        __syncthreads();
    }

    // ---- epilogue: ctx = O/l + maskV, stored fp16 hi/lo
    float inv0 = 1.0f / l0, inv1 = 1.0f / l1;
    int q_lo = q0 + gid;
    int q_hi = q_lo + 8;
    #pragma unroll
    for (int nt = 0; nt < 8; nt++) {
        int hs = nt*8 + tig*2;
        float mv0 = gMV[ph*HSZ + hs], mv1 = gMV[ph*HSZ + hs + 1];
        float v0 = oacc[nt][0]*inv0 + mv0, v1 = oacc[nt][1]*inv0 + mv1;
        float v2 = oacc[nt][2]*inv1 + mv0, v3 = oacc[nt][3]*inv1 + mv1;
        size_t o0 = ((size_t)p*NN + q_lo) * DD + h*HSZ + hs;
        size_t o1 = ((size_t)p*NN + q_hi) * DD + h*HSZ + hs;
        uint32_t whi, wlo;
        split2h(v0, v1, whi, wlo);
        *(uint32_t*)&gCh[o0] = whi; *(uint32_t*)&gCl[o0] = wlo;
        split2h(v2, v3, whi, wlo);
        *(uint32_t*)&gCh[o1] = whi; *(uint32_t*)&gCl[o1] = wlo;
    }
}

extern "C" void kernel_launch(void* const* d_in, const int* in_sizes, int n_in,
                              void* d_out, int out_size) {
    const float* X      = (const float*)d_in[0];
    const float* mask   = (const float*)d_in[1];
    const float* qkv_w  = (const float*)d_in[2];
    const float* qkv_b  = (const float*)d_in[3];
    const float* proj_w = (const float*)d_in[4];
    const float* proj_b = (const float*)d_in[5];
    float* out = (float*)d_out;

    cudaFuncSetAttribute(qkv_gemm, cudaFuncAttributeMaxDynamicSharedMemorySize, QKV_SMEM);
    cudaFuncSetAttribute(proj_gemm, cudaFuncAttributeMaxDynamicSharedMemorySize, PROJ_SMEM);
    cudaFuncSetAttribute(attn_mma, cudaFuncAttributeMaxDynamicSharedMemorySize, ATTN_SMEM);

    __nv_bfloat16 *xhi, *xlo, *wqh, *wql;
    __half *wp;
    cudaGetSymbolAddress((void**)&xhi, gXhi);
    cudaGetSymbolAddress((void**)&xlo, gXlo);
    cudaGetSymbolAddress((void**)&wqh, gWqh);
    cudaGetSymbolAddress((void**)&wql, gWql);
    cudaGetSymbolAddress((void**)&wp, gWp);

    split_kernel<<<(PP*NN*DD/4 + 255)/256, 256>>>(X, xhi, xlo, PP*NN*DD/4);
    tsplit_kernel<<<dim3(3*DD/32, DD/32), dim3(32,8)>>>(qkv_w, wqh, wql, DD, 3*DD);
    ttrans_kernel<<<dim3(DD/32, DD/32), dim3(32,8)>>>(proj_w, wp, DD, DD);
    qkv_gemm<<<dim3(3*DD/128, PP*NN/128), 256, QKV_SMEM>>>(qkv_b);
    maskv_kernel<<<PP*HH, 256>>>(mask);
    attn_mma<<<dim3(NN/128, HH, PP), 256, ATTN_SMEM>>>();
    proj_gemm<<<dim3(DD/128, PP*NN/128), 256, PROJ_SMEM>>>(proj_b, out);
}

// round 16
// speedup vs baseline: 1.3391x; 1.1110x over previous
#include <cuda_runtime.h>
#include <cuda_bf16.h>
#include <cuda_fp16.h>
#include <cstdint>

#define PP 8
#define NN 1024
#define DD 768
#define HH 12
#define HSZ 64
#define SCLOG2 11.5423594967f   // 8 * log2(e)

// ---- scratch (static) ----
__device__ float gMV[PP*HH*HSZ];
__device__ __nv_bfloat16 gXhi[PP*NN*DD];
__device__ __nv_bfloat16 gXlo[PP*NN*DD];
__device__ __nv_bfloat16 gWqh[3*DD*DD];
__device__ __nv_bfloat16 gWql[3*DD*DD];
__device__ __half gWp[DD*DD];          // proj_w transposed, single fp16
__device__ __half gCt[PP*NN*DD];       // ctx single fp16
// attention: Q,K bf16 hi/lo [ph][n][hs]; V transposed single fp16 [ph][hs][n]
__device__ __nv_bfloat16 gQh[PP*HH*NN*HSZ];
__device__ __nv_bfloat16 gQl[PP*HH*NN*HSZ];
__device__ __nv_bfloat16 gKh[PP*HH*NN*HSZ];
__device__ __nv_bfloat16 gKl[PP*HH*NN*HSZ];
__device__ __half gVt[PP*HH*NN*HSZ];

// ================= helpers =================
__device__ __forceinline__ uint32_t smem_u32(const void* p) {
    uint32_t a;
    asm("{ .reg .u64 t; cvta.to.shared.u64 t, %1; cvt.u32.u64 %0, t; }" : "=r"(a) : "l"(p));
    return a;
}
__device__ __forceinline__ uint32_t lds32(uint32_t a) {
    uint32_t v;
    asm volatile("ld.shared.b32 %0, [%1];" : "=r"(v) : "r"(a));
    return v;
}
#define CP16(saddr, gptr) \
    asm volatile("cp.async.cg.shared.global [%0], [%1], 16;" :: "r"(saddr), "l"(gptr))
#define CP_COMMIT() asm volatile("cp.async.commit_group;" ::: "memory")
#define CP_WAIT1()  asm volatile("cp.async.wait_group 1;" ::: "memory")
#define CP_WAIT0()  asm volatile("cp.async.wait_group 0;" ::: "memory")

__device__ __forceinline__ void mma_bf(float* c, const uint32_t* a, const uint32_t* b) {
    asm volatile("mma.sync.aligned.m16n8k16.row.col.f32.bf16.bf16.f32 "
                 "{%0,%1,%2,%3}, {%4,%5,%6,%7}, {%8,%9}, {%0,%1,%2,%3};"
                 : "+f"(c[0]), "+f"(c[1]), "+f"(c[2]), "+f"(c[3])
                 : "r"(a[0]), "r"(a[1]), "r"(a[2]), "r"(a[3]), "r"(b[0]), "r"(b[1]));
}
__device__ __forceinline__ void mma_hf(float* c, const uint32_t* a, const uint32_t* b) {
    asm volatile("mma.sync.aligned.m16n8k16.row.col.f32.f16.f16.f32 "
                 "{%0,%1,%2,%3}, {%4,%5,%6,%7}, {%8,%9}, {%0,%1,%2,%3};"
                 : "+f"(c[0]), "+f"(c[1]), "+f"(c[2]), "+f"(c[3])
                 : "r"(a[0]), "r"(a[1]), "r"(a[2]), "r"(a[3]), "r"(b[0]), "r"(b[1]));
}
// bf16 pack / split
__device__ __forceinline__ uint32_t pack2(float v0, float v1) {
    uint32_t r;
    asm("cvt.rn.bf16x2.f32 %0, %1, %2;" : "=r"(r) : "f"(v1), "f"(v0));
    return r;
}
__device__ __forceinline__ void split2(float v0, float v1, uint32_t& phi, uint32_t& plo) {
    phi = pack2(v0, v1);
    float h0 = __uint_as_float(phi << 16);
    float h1 = __uint_as_float(phi & 0xffff0000u);
    plo = pack2(v0 - h0, v1 - h1);
}
// fp16 pack
__device__ __forceinline__ uint32_t pack2h(float v0, float v1) {
    uint32_t r;
    asm("cvt.rn.f16x2.f32 %0, %1, %2;" : "=r"(r) : "f"(v1), "f"(v0));
    return r;
}

// ================= split / transpose =================
__global__ void split_kernel(const float* __restrict__ src,
                             __nv_bfloat16* __restrict__ hi,
                             __nv_bfloat16* __restrict__ lo, int n4) {
    int i = blockIdx.x * blockDim.x + threadIdx.x;
    if (i >= n4) return;
    float4 v = ((const float4*)src)[i];
    uint32_t h[2], l[2];
    split2(v.x, v.y, h[0], l[0]);
    split2(v.z, v.w, h[1], l[1]);
    ((uint2*)hi)[i] = make_uint2(h[0], h[1]);
    ((uint2*)lo)[i] = make_uint2(l[0], l[1]);
}

// W[K][N] -> T[N][K], bf16 hi/lo
__global__ void tsplit_kernel(const float* __restrict__ W,
                              __nv_bfloat16* __restrict__ Th,
                              __nv_bfloat16* __restrict__ Tl, int K, int N) {
    __shared__ float t[32][33];
    int k0 = blockIdx.y * 32, n0 = blockIdx.x * 32;
    int tx = threadIdx.x, ty = threadIdx.y;
    #pragma unroll
    for (int i = 0; i < 4; i++)
        t[ty + 8*i][tx] = W[(size_t)(k0 + ty + 8*i) * N + n0 + tx];
    __syncthreads();
    #pragma unroll
    for (int i = 0; i < 4; i++) {
        float x = t[tx][ty + 8*i];
        __nv_bfloat16 h = __float2bfloat16_rn(x);
        __nv_bfloat16 l = __float2bfloat16_rn(x - __bfloat162float(h));
        size_t o = (size_t)(n0 + ty + 8*i) * K + k0 + tx;
        Th[o] = h; Tl[o] = l;
    }
}

// W[K][N] -> T[N][K], single fp16
__global__ void ttrans_kernel(const float* __restrict__ W,
                              __half* __restrict__ Th, int K, int N) {
    __shared__ float t[32][33];
    int k0 = blockIdx.y * 32, n0 = blockIdx.x * 32;
    int tx = threadIdx.x, ty = threadIdx.y;
    #pragma unroll
    for (int i = 0; i < 4; i++)
        t[ty + 8*i][tx] = W[(size_t)(k0 + ty + 8*i) * N + n0 + tx];
    __syncthreads();
    #pragma unroll
    for (int i = 0; i < 4; i++) {
        size_t o = (size_t)(n0 + ty + 8*i) * K + k0 + tx;
        Th[o] = __float2half_rn(t[tx][ty + 8*i]);
    }
}

// ================= QKV GEMM: bf16x3 (accuracy-critical) =================
#define PADK 40
#define TILE_E (128*PADK)
#define QBUF_BYTES (4*TILE_E*2)       // 40960 B per buffer
#define QKV_SMEM (2*QBUF_BYTES)       // 81920 B

__global__ __launch_bounds__(256, 2) void qkv_gemm(const float* __restrict__ bias) {
    extern __shared__ __align__(16) char smem[];
    uint32_t sb = smem_u32(smem);
    int tid = threadIdx.x, wid = tid >> 5, lane = tid & 31;
    int wm = wid & 3, wn = wid >> 2;
    int row0 = blockIdx.y * 128, col0 = blockIdx.x * 128;
    int gid = lane >> 2, tig = lane & 3;

    const __nv_bfloat16* srcs[4] = {gXhi, gXlo, gWqh, gWql};

    float acc[2][8][4];
    #pragma unroll
    for (int i = 0; i < 2; i++)
        #pragma unroll
        for (int j = 0; j < 8; j++)
            #pragma unroll
            for (int q = 0; q < 4; q++) acc[i][j][q] = 0.f;

    auto fill = [&](int s, int c) {
        int k0 = c * 32;
        uint32_t sbase = sb + s * QBUF_BYTES;
        #pragma unroll
        for (int t = 0; t < 4; t++) {
            const __nv_bfloat16* src = srcs[t];
            int rbase = (t < 2) ? row0 : col0;
            #pragma unroll
            for (int j = 0; j < 2; j++) {
                int e = j * 256 + tid;
                int r = e >> 2, v = e & 3;
                uint32_t daddr = sbase + (uint32_t)(t * TILE_E + r * PADK + v * 8) * 2;
                CP16(daddr, src + (size_t)(rbase + r) * DD + k0 + v * 8);
            }
        }
        CP_COMMIT();
    };

    fill(0, 0);
    for (int c = 0; c < 24; c++) {
        if (c < 23) fill((c + 1) & 1, c + 1);
        if (c < 23) CP_WAIT1(); else CP_WAIT0();
        __syncthreads();

        uint32_t base = sb + (c & 1) * QBUF_BYTES;
        uint32_t Ahb = base, Alb = base + TILE_E*2;
        uint32_t Bhb = base + 2*TILE_E*2, Blb = Bhb + TILE_E*2;

        #pragma unroll
        for (int ks = 0; ks < 2; ks++) {
            int kcol = ks * 16 + tig * 2;
            uint32_t ah[2][4], al[2][4];
            #pragma unroll
            for (int mt = 0; mt < 2; mt++) {
                int r = wm * 32 + mt * 16 + gid;
                uint32_t o = (uint32_t)(r * PADK + kcol) * 2;
                ah[mt][0] = lds32(Ahb + o);
                ah[mt][1] = lds32(Ahb + o + 8*PADK*2);
                ah[mt][2] = lds32(Ahb + o + 16);
                ah[mt][3] = lds32(Ahb + o + 8*PADK*2 + 16);
                al[mt][0] = lds32(Alb + o);
                al[mt][1] = lds32(Alb + o + 8*PADK*2);
                al[mt][2] = lds32(Alb + o + 16);
                al[mt][3] = lds32(Alb + o + 8*PADK*2 + 16);
            }
            #pragma unroll
            for (int half = 0; half < 2; half++) {
                uint32_t bh[4][2], bl[4][2];
                #pragma unroll
                for (int nt = 0; nt < 4; nt++) {
                    int n = wn * 64 + half * 32 + nt * 8 + gid;
                    uint32_t o = (uint32_t)(n * PADK + kcol) * 2;
                    bh[nt][0] = lds32(Bhb + o);
                    bh[nt][1] = lds32(Bhb + o + 16);
                    bl[nt][0] = lds32(Blb + o);
                    bl[nt][1] = lds32(Blb + o + 16);
                }
                #pragma unroll
                for (int mt = 0; mt < 2; mt++)
                    #pragma unroll
                    for (int nt = 0; nt < 4; nt++)
                        mma_bf(acc[mt][half*4 + nt], ah[mt], bh[nt]);
                #pragma unroll
                for (int mt = 0; mt < 2; mt++)
                    #pragma unroll
                    for (int nt = 0; nt < 4; nt++)
                        mma_bf(acc[mt][half*4 + nt], ah[mt], bl[nt]);
                #pragma unroll
                for (int mt = 0; mt < 2; mt++)
                    #pragma unroll
                    for (int nt = 0; nt < 4; nt++)
                        mma_bf(acc[mt][half*4 + nt], al[mt], bh[nt]);
            }
        }
        __syncthreads();
    }

    // ---- epilogue: Q,K bf16 hi/lo; V transposed single fp16 ----
    #pragma unroll
    for (int mt = 0; mt < 2; mt++) {
        int m_lo = row0 + wm * 32 + mt * 16 + gid;
        int m_hi = m_lo + 8;
        #pragma unroll
        for (int j = 0; j < 8; j++) {
            int nc = col0 + wn * 64 + (j >> 2) * 32 + (j & 3) * 8 + tig * 2;
            float b0 = bias[nc], b1 = bias[nc + 1];
            float* cc = acc[mt][j];
            float v0 = cc[0] + b0, v1 = cc[1] + b1;
            float v2 = cc[2] + b0, v3 = cc[3] + b1;
            int which = (nc >= 2*DD) ? 2 : ((nc >= DD) ? 1 : 0);
            int rem = nc - which * DD;
            int h = rem >> 6, hs = rem & 63;
            int p0 = m_lo >> 10, n0 = m_lo & 1023;
            int p1 = m_hi >> 10, n1 = m_hi & 1023;
            int ph0 = p0 * HH + h, ph1 = p1 * HH + h;
            if (which == 2) {
                size_t r0 = ((size_t)ph0 * HSZ + hs) * NN;
                size_t r1 = ((size_t)ph1 * HSZ + hs) * NN;
                gVt[r0 + n0]      = __float2half_rn(v0);
                gVt[r0 + NN + n0] = __float2half_rn(v1);
                gVt[r1 + n1]      = __float2half_rn(v2);
                gVt[r1 + NN + n1] = __float2half_rn(v3);
            } else {
                __nv_bfloat16* dh = which ? gKh : gQh;
                __nv_bfloat16* dl = which ? gKl : gQl;
                size_t o0 = (((size_t)ph0 << 10) + n0) * HSZ + hs;
                size_t o1 = (((size_t)ph1 << 10) + n1) * HSZ + hs;
                uint32_t whi, wlo;
                split2(v0, v1, whi, wlo);
                *(uint32_t*)&dh[o0] = whi; *(uint32_t*)&dl[o0] = wlo;
                split2(v2, v3, whi, wlo);
                *(uint32_t*)&dh[o1] = whi; *(uint32_t*)&dl[o1] = wlo;
            }
        }
    }
}

// ================= proj GEMM: fp16 1-term =================
#define PBUF_BYTES (2*TILE_E*2)       // 20480 B per buffer
#define PROJ_SMEM (2*PBUF_BYTES)      // 40960 B

__global__ __launch_bounds__(256, 2) void proj_gemm(const float* __restrict__ bias,
                                                    float* __restrict__ out) {
    extern __shared__ __align__(16) char smem[];
    uint32_t sb = smem_u32(smem);
    int tid = threadIdx.x, wid = tid >> 5, lane = tid & 31;
    int wm = wid & 3, wn = wid >> 2;
    int row0 = blockIdx.y * 128, col0 = blockIdx.x * 128;
    int gid = lane >> 2, tig = lane & 3;

    const __half* srcs[2] = {gCt, gWp};

    float acc[2][8][4];
    #pragma unroll
    for (int i = 0; i < 2; i++)
        #pragma unroll
        for (int j = 0; j < 8; j++)
            #pragma unroll
            for (int q = 0; q < 4; q++) acc[i][j][q] = 0.f;

    auto fill = [&](int s, int c) {
        int k0 = c * 32;
        uint32_t sbase = sb + s * PBUF_BYTES;
        #pragma unroll
        for (int t = 0; t < 2; t++) {
            const __half* src = srcs[t];
            int rbase = (t < 1) ? row0 : col0;
            #pragma unroll
            for (int j = 0; j < 2; j++) {
                int e = j * 256 + tid;
                int r = e >> 2, v = e & 3;
                uint32_t daddr = sbase + (uint32_t)(t * TILE_E + r * PADK + v * 8) * 2;
                CP16(daddr, src + (size_t)(rbase + r) * DD + k0 + v * 8);
            }
        }
        CP_COMMIT();
    };

    fill(0, 0);
    for (int c = 0; c < 24; c++) {
        if (c < 23) fill((c + 1) & 1, c + 1);
        if (c < 23) CP_WAIT1(); else CP_WAIT0();
        __syncthreads();

        uint32_t base = sb + (c & 1) * PBUF_BYTES;
        uint32_t Ab = base, Bb = base + TILE_E*2;

        #pragma unroll
        for (int ks = 0; ks < 2; ks++) {
            int kcol = ks * 16 + tig * 2;
            uint32_t aa[2][4];
            #pragma unroll
            for (int mt = 0; mt < 2; mt++) {
                int r = wm * 32 + mt * 16 + gid;
                uint32_t o = (uint32_t)(r * PADK + kcol) * 2;
                aa[mt][0] = lds32(Ab + o);
                aa[mt][1] = lds32(Ab + o + 8*PADK*2);
                aa[mt][2] = lds32(Ab + o + 16);
                aa[mt][3] = lds32(Ab + o + 8*PADK*2 + 16);
            }
            #pragma unroll
            for (int half = 0; half < 2; half++) {
                uint32_t bb[4][2];
                #pragma unroll
                for (int nt = 0; nt < 4; nt++) {
                    int n = wn * 64 + half * 32 + nt * 8 + gid;
                    uint32_t o = (uint32_t)(n * PADK + kcol) * 2;
                    bb[nt][0] = lds32(Bb + o);
                    bb[nt][1] = lds32(Bb + o + 16);
                }
                #pragma unroll
                for (int mt = 0; mt < 2; mt++)
                    #pragma unroll
                    for (int nt = 0; nt < 4; nt++)
                        mma_hf(acc[mt][half*4 + nt], aa[mt], bb[nt]);
            }
        }
        __syncthreads();
    }

    #pragma unroll
    for (int mt = 0; mt < 2; mt++) {
        int m_lo = row0 + wm * 32 + mt * 16 + gid;
        int m_hi = m_lo + 8;
        #pragma unroll
        for (int j = 0; j < 8; j++) {
            int nc = col0 + wn * 64 + (j >> 2) * 32 + (j & 3) * 8 + tig * 2;
            float b0 = bias[nc], b1 = bias[nc + 1];
            float* cc = acc[mt][j];
            *(float2*)&out[(size_t)m_lo * DD + nc] = make_float2(cc[0] + b0, cc[1] + b1);
            *(float2*)&out[(size_t)m_hi * DD + nc] = make_float2(cc[2] + b0, cc[3] + b1);
        }
    }
}

// ================= post-softmax mask term =================
__global__ void maskv_kernel(const float* __restrict__ mask) {
    int ph = blockIdx.x;
    int p = ph / HH;
    int w = threadIdx.x >> 5, lane = threadIdx.x & 31;
    const float* mp = mask + (size_t)p * NN;
    #pragma unroll
    for (int i = 0; i < 8; i++) {
        int hs = w * 8 + i;
        const __half* vh = gVt + ((size_t)ph * HSZ + hs) * NN;
        float acc = 0.f;
        for (int k = lane; k < NN; k += 32)
            acc += mp[k] * __half2float(vh[k]);
        #pragma unroll
        for (int s = 16; s > 0; s >>= 1) acc += __shfl_xor_sync(0xffffffffu, acc, s);
        if (lane == 0) gMV[ph * HSZ + hs] = acc;
    }
}

// ================= flash attention: S bf16x3, PV fp16x1 =================
// CTA = (p, h, 128 q-rows), 256 threads = 8 warps x 16 q-rows.
// K-block 64, double buffered, 2 CTAs/SM.
// smem per buffer: Kh[64][72], Kl[64][72] bf16, Vt[64][72] fp16.
#define AKS 72
#define KTILE_B (64*AKS*2)          // 9216 B
#define ABUF_B (3*KTILE_B)          // 27648 B
#define ATTN_SMEM (2*ABUF_B)        // 55296 B

__global__ __launch_bounds__(256, 2) void attn_mma() {
    extern __shared__ __align__(16) char smem[];
    uint32_t sb = smem_u32(smem);
    int tid = threadIdx.x, wid = tid >> 5, lane = tid & 31;
    int gid = lane >> 2, tig = lane & 3;
    int qb = blockIdx.x, h = blockIdx.y, p = blockIdx.z;
    int ph = p * HH + h;
    int q0 = qb * 128 + wid * 16;

    // ---- preload Q fragments (bf16 hi/lo)
    uint32_t qh[4][4], ql[4][4];
    {
        const __nv_bfloat16* base_h = gQh + ((size_t)ph * NN + q0) * HSZ;
        const __nv_bfloat16* base_l = gQl + ((size_t)ph * NN + q0) * HSZ;
        #pragma unroll
        for (int kk = 0; kk < 4; kk++) {
            int c = kk * 16 + tig * 2;
            qh[kk][0] = *(const uint32_t*)(base_h + (size_t)gid * HSZ + c);
            qh[kk][1] = *(const uint32_t*)(base_h + (size_t)(gid+8) * HSZ + c);
            qh[kk][2] = *(const uint32_t*)(base_h + (size_t)gid * HSZ + c + 8);
            qh[kk][3] = *(const uint32_t*)(base_h + (size_t)(gid+8) * HSZ + c + 8);
            ql[kk][0] = *(const uint32_t*)(base_l + (size_t)gid * HSZ + c);
            ql[kk][1] = *(const uint32_t*)(base_l + (size_t)(gid+8) * HSZ + c);
            ql[kk][2] = *(const uint32_t*)(base_l + (size_t)gid * HSZ + c + 8);
            ql[kk][3] = *(const uint32_t*)(base_l + (size_t)(gid+8) * HSZ + c + 8);
        }
    }

    float oacc[8][4];
    #pragma unroll
    for (int i = 0; i < 8; i++)
        #pragma unroll
        for (int j = 0; j < 4; j++) oacc[i][j] = 0.f;
    float m0 = -1e30f, m1 = -1e30f, l0 = 0.f, l1 = 0.f;

    const __nv_bfloat16* Kh_g = gKh + (size_t)ph * NN * HSZ;
    const __nv_bfloat16* Kl_g = gKl + (size_t)ph * NN * HSZ;
    const __half* V_g = gVt + (size_t)ph * HSZ * NN;

    auto fill = [&](int s, int kb) {
        uint32_t base = sb + s * ABUF_B;
        #pragma unroll
        for (int j = 0; j < 2; j++) {
            int e = j * 256 + tid;
            int r = e >> 3, ch = e & 7;
            uint32_t d = base + (uint32_t)(r * AKS + ch * 8) * 2;
            CP16(d, Kh_g + (size_t)(kb*64 + r) * HSZ + ch * 8);
            CP16(d + KTILE_B, Kl_g + (size_t)(kb*64 + r) * HSZ + ch * 8);
        }
        #pragma unroll
        for (int j = 0; j < 2; j++) {
            int e = j * 256 + tid;
            int r = e >> 3, ch = e & 7;
            uint32_t d = base + 2*KTILE_B + (uint32_t)(r * AKS + ch * 8) * 2;
            CP16(d, V_g + (size_t)r * NN + kb*64 + ch * 8);
        }
        CP_COMMIT();
    };

    fill(0, 0);
    for (int kb = 0; kb < 16; kb++) {
        if (kb < 15) fill((kb + 1) & 1, kb + 1);
        if (kb < 15) CP_WAIT1(); else CP_WAIT0();
        __syncthreads();

        uint32_t base = sb + (kb & 1) * ABUF_B;
        uint32_t Khb = base, Klb = base + KTILE_B, Vb = base + 2*KTILE_B;

        // ---- S = Q K^T, bf16 3-term
        float sacc[8][4];
        #pragma unroll
        for (int nt = 0; nt < 8; nt++)
            #pragma unroll
            for (int j = 0; j < 4; j++) sacc[nt][j] = 0.f;
        #pragma unroll
        for (int kk = 0; kk < 4; kk++) {
            uint32_t co = (uint32_t)(kk*16 + tig*2) * 2;
            #pragma unroll
            for (int g = 0; g < 2; g++) {
                uint32_t bh[4][2], bl[4][2];
                #pragma unroll
                for (int n4 = 0; n4 < 4; n4++) {
                    uint32_t ro = (uint32_t)(((g*4 + n4)*8 + gid) * AKS) * 2;
                    bh[n4][0] = lds32(Khb + ro + co);
                    bh[n4][1] = lds32(Khb + ro + co + 16);
                    bl[n4][0] = lds32(Klb + ro + co);
                    bl[n4][1] = lds32(Klb + ro + co + 16);
                }
                #pragma unroll
                for (int n4 = 0; n4 < 4; n4++) mma_bf(sacc[g*4+n4], qh[kk], bh[n4]);
                #pragma unroll
                for (int n4 = 0; n4 < 4; n4++) mma_bf(sacc[g*4+n4], qh[kk], bl[n4]);
                #pragma unroll
                for (int n4 = 0; n4 < 4; n4++) mma_bf(sacc[g*4+n4], ql[kk], bh[n4]);
            }
        }

        // ---- online softmax
        float mx0 = -1e30f, mx1 = -1e30f;
        #pragma unroll
        for (int nt = 0; nt < 8; nt++) {
            mx0 = fmaxf(mx0, fmaxf(sacc[nt][0], sacc[nt][1]));
            mx1 = fmaxf(mx1, fmaxf(sacc[nt][2], sacc[nt][3]));
        }
        mx0 = fmaxf(mx0, __shfl_xor_sync(0xffffffffu, mx0, 1));
        mx0 = fmaxf(mx0, __shfl_xor_sync(0xffffffffu, mx0, 2));
        mx1 = fmaxf(mx1, __shfl_xor_sync(0xffffffffu, mx1, 1));
        mx1 = fmaxf(mx1, __shfl_xor_sync(0xffffffffu, mx1, 2));
        float nm0 = fmaxf(m0, mx0), nm1 = fmaxf(m1, mx1);
        float corr0 = exp2f((m0 - nm0) * SCLOG2);
        float corr1 = exp2f((m1 - nm1) * SCLOG2);
        m0 = nm0; m1 = nm1;
        float rs0 = 0.f, rs1 = 0.f;
        #pragma unroll
        for (int nt = 0; nt < 8; nt++) {
            sacc[nt][0] = exp2f((sacc[nt][0] - nm0) * SCLOG2);
            sacc[nt][1] = exp2f((sacc[nt][1] - nm0) * SCLOG2);
            sacc[nt][2] = exp2f((sacc[nt][2] - nm1) * SCLOG2);
            sacc[nt][3] = exp2f((sacc[nt][3] - nm1) * SCLOG2);
            rs0 += sacc[nt][0] + sacc[nt][1];
            rs1 += sacc[nt][2] + sacc[nt][3];
        }
        rs0 += __shfl_xor_sync(0xffffffffu, rs0, 1);
        rs0 += __shfl_xor_sync(0xffffffffu, rs0, 2);
        rs1 += __shfl_xor_sync(0xffffffffu, rs1, 1);
        rs1 += __shfl_xor_sync(0xffffffffu, rs1, 2);
        l0 = l0 * corr0 + rs0;
        l1 = l1 * corr1 + rs1;
        #pragma unroll
        for (int nt = 0; nt < 8; nt++) {
            oacc[nt][0] *= corr0; oacc[nt][1] *= corr0;
            oacc[nt][2] *= corr1; oacc[nt][3] *= corr1;
        }

        // ---- O += P V, fp16 1-term (P single fp16, V single fp16)
        #pragma unroll
        for (int kblk = 0; kblk < 4; kblk++) {
            uint32_t ap[4];
            ap[0] = pack2h(sacc[2*kblk][0],   sacc[2*kblk][1]);
            ap[1] = pack2h(sacc[2*kblk][2],   sacc[2*kblk][3]);
            ap[2] = pack2h(sacc[2*kblk+1][0], sacc[2*kblk+1][1]);
            ap[3] = pack2h(sacc[2*kblk+1][2], sacc[2*kblk+1][3]);
            uint32_t co = (uint32_t)(kblk*16 + tig*2) * 2;
            #pragma unroll
            for (int g = 0; g < 2; g++) {
                uint32_t bb[4][2];
                #pragma unroll
                for (int n4 = 0; n4 < 4; n4++) {
                    uint32_t ro = (uint32_t)(((g*4 + n4)*8 + gid) * AKS) * 2;
                    bb[n4][0] = lds32(Vb + ro + co);
                    bb[n4][1] = lds32(Vb + ro + co + 16);
                }
                #pragma unroll
                for (int n4 = 0; n4 < 4; n4++) mma_hf(oacc[g*4+n4], ap, bb[n4]);
            }
        }
        __syncthreads();
    }

    // ---- epilogue: ctx = O/l + maskV, stored single fp16
    float inv0 = 1.0f / l0, inv1 = 1.0f / l1;
    int q_lo = q0 + gid;
    int q_hi = q_lo + 8;
    #pragma unroll
    for (int nt = 0; nt < 8; nt++) {
        int hs = nt*8 + tig*2;
        float mv0 = gMV[ph*HSZ + hs], mv1 = gMV[ph*HSZ + hs + 1];
        float v0 = oacc[nt][0]*inv0 + mv0, v1 = oacc[nt][1]*inv0 + mv1;
        float v2 = oacc[nt][2]*inv1 + mv0, v3 = oacc[nt][3]*inv1 + mv1;
        size_t o0 = ((size_t)p*NN + q_lo) * DD + h*HSZ + hs;
        size_t o1 = ((size_t)p*NN + q_hi) * DD + h*HSZ + hs;
        *(uint32_t*)&gCt[o0] = pack2h(v0, v1);
        *(uint32_t*)&gCt[o1] = pack2h(v2, v3);
    }
}

extern "C" void kernel_launch(void* const* d_in, const int* in_sizes, int n_in,
                              void* d_out, int out_size) {
    const float* X      = (const float*)d_in[0];
    const float* mask   = (const float*)d_in[1];
    const float* qkv_w  = (const float*)d_in[2];
    const float* qkv_b  = (const float*)d_in[3];
    const float* proj_w = (const float*)d_in[4];
    const float* proj_b = (const float*)d_in[5];
    float* out = (float*)d_out;

    cudaFuncSetAttribute(qkv_gemm, cudaFuncAttributeMaxDynamicSharedMemorySize, QKV_SMEM);
    cudaFuncSetAttribute(proj_gemm, cudaFuncAttributeMaxDynamicSharedMemorySize, PROJ_SMEM);
    cudaFuncSetAttribute(attn_mma, cudaFuncAttributeMaxDynamicSharedMemorySize, ATTN_SMEM);

    __nv_bfloat16 *xhi, *xlo, *wqh, *wql;
    __half *wp;
    cudaGetSymbolAddress((void**)&xhi, gXhi);
    cudaGetSymbolAddress((void**)&xlo, gXlo);
    cudaGetSymbolAddress((void**)&wqh, gWqh);
    cudaGetSymbolAddress((void**)&wql, gWql);
    cudaGetSymbolAddress((void**)&wp, gWp);

    split_kernel<<<(PP*NN*DD/4 + 255)/256, 256>>>(X, xhi, xlo, PP*NN*DD/4);
    tsplit_kernel<<<dim3(3*DD/32, DD/32), dim3(32,8)>>>(qkv_w, wqh, wql, DD, 3*DD);
    ttrans_kernel<<<dim3(DD/32, DD/32), dim3(32,8)>>>(proj_w, wp, DD, DD);
    qkv_gemm<<<dim3(3*DD/128, PP*NN/128), 256, QKV_SMEM>>>(qkv_b);
    maskv_kernel<<<PP*HH, 256>>>(mask);
    attn_mma<<<dim3(NN/128, HH, PP), 256, ATTN_SMEM>>>();
    proj_gemm<<<dim3(DD/128, PP*NN/128), 256, PROJ_SMEM>>>(proj_b, out);
}

// round 17
// speedup vs baseline: 1.4103x; 1.0532x over previous
#include <cuda_runtime.h>
#include <cuda_bf16.h>
#include <cuda_fp16.h>
#include <cstdint>

#define PP 8
#define NN 1024
#define DD 768
#define HH 12
#define HSZ 64
#define SCLOG2 11.5423594967f   // 8 * log2(e)

// ---- scratch (static) ----
__device__ float gMV[PP*HH*HSZ];
__device__ __nv_bfloat16 gXhi[PP*NN*DD];
__device__ __nv_bfloat16 gXlo[PP*NN*DD];
__device__ __half gXf[PP*NN*DD];       // X single fp16 (for V GEMM)
__device__ __nv_bfloat16 gWqh[2*DD*DD];  // qkv_w cols 0..1535 transposed, bf16 hi/lo
__device__ __nv_bfloat16 gWql[2*DD*DD];
__device__ __half gWv[DD*DD];          // qkv_w cols 1536..2303 transposed, fp16
__device__ __half gWp[DD*DD];          // proj_w transposed, fp16
__device__ __half gCt[PP*NN*DD];       // ctx single fp16
// attention: Q,K bf16 hi/lo [ph][n][hs]; V transposed single fp16 [ph][hs][n]
__device__ __nv_bfloat16 gQh[PP*HH*NN*HSZ];
__device__ __nv_bfloat16 gQl[PP*HH*NN*HSZ];
__device__ __nv_bfloat16 gKh[PP*HH*NN*HSZ];
__device__ __nv_bfloat16 gKl[PP*HH*NN*HSZ];
__device__ __half gVt[PP*HH*NN*HSZ];

// ================= helpers =================
__device__ __forceinline__ uint32_t smem_u32(const void* p) {
    uint32_t a;
    asm("{ .reg .u64 t; cvta.to.shared.u64 t, %1; cvt.u32.u64 %0, t; }" : "=r"(a) : "l"(p));
    return a;
}
__device__ __forceinline__ uint32_t lds32(uint32_t a) {
    uint32_t v;
    asm volatile("ld.shared.b32 %0, [%1];" : "=r"(v) : "r"(a));
    return v;
}
#define CP16(saddr, gptr) \
    asm volatile("cp.async.cg.shared.global [%0], [%1], 16;" :: "r"(saddr), "l"(gptr))
#define CP_COMMIT() asm volatile("cp.async.commit_group;" ::: "memory")
#define CP_WAIT1()  asm volatile("cp.async.wait_group 1;" ::: "memory")
#define CP_WAIT0()  asm volatile("cp.async.wait_group 0;" ::: "memory")

__device__ __forceinline__ void mma_bf(float* c, const uint32_t* a, const uint32_t* b) {
    asm volatile("mma.sync.aligned.m16n8k16.row.col.f32.bf16.bf16.f32 "
                 "{%0,%1,%2,%3}, {%4,%5,%6,%7}, {%8,%9}, {%0,%1,%2,%3};"
                 : "+f"(c[0]), "+f"(c[1]), "+f"(c[2]), "+f"(c[3])
                 : "r"(a[0]), "r"(a[1]), "r"(a[2]), "r"(a[3]), "r"(b[0]), "r"(b[1]));
}
__device__ __forceinline__ void mma_hf(float* c, const uint32_t* a, const uint32_t* b) {
    asm volatile("mma.sync.aligned.m16n8k16.row.col.f32.f16.f16.f32 "
                 "{%0,%1,%2,%3}, {%4,%5,%6,%7}, {%8,%9}, {%0,%1,%2,%3};"
                 : "+f"(c[0]), "+f"(c[1]), "+f"(c[2]), "+f"(c[3])
                 : "r"(a[0]), "r"(a[1]), "r"(a[2]), "r"(a[3]), "r"(b[0]), "r"(b[1]));
}
// bf16 pack / split
__device__ __forceinline__ uint32_t pack2(float v0, float v1) {
    uint32_t r;
    asm("cvt.rn.bf16x2.f32 %0, %1, %2;" : "=r"(r) : "f"(v1), "f"(v0));
    return r;
}
__device__ __forceinline__ void split2(float v0, float v1, uint32_t& phi, uint32_t& plo) {
    phi = pack2(v0, v1);
    float h0 = __uint_as_float(phi << 16);
    float h1 = __uint_as_float(phi & 0xffff0000u);
    plo = pack2(v0 - h0, v1 - h1);
}
// fp16 pack
__device__ __forceinline__ uint32_t pack2h(float v0, float v1) {
    uint32_t r;
    asm("cvt.rn.f16x2.f32 %0, %1, %2;" : "=r"(r) : "f"(v1), "f"(v0));
    return r;
}

// ================= split / transpose =================
__global__ void split_kernel(const float* __restrict__ src,
                             __nv_bfloat16* __restrict__ hi,
                             __nv_bfloat16* __restrict__ lo,
                             __half* __restrict__ xf, int n4) {
    int i = blockIdx.x * blockDim.x + threadIdx.x;
    if (i >= n4) return;
    float4 v = ((const float4*)src)[i];
    uint32_t h[2], l[2];
    split2(v.x, v.y, h[0], l[0]);
    split2(v.z, v.w, h[1], l[1]);
    ((uint2*)hi)[i] = make_uint2(h[0], h[1]);
    ((uint2*)lo)[i] = make_uint2(l[0], l[1]);
    ((uint2*)xf)[i] = make_uint2(pack2h(v.x, v.y), pack2h(v.z, v.w));
}

// W[k][ld] cols [colOff, colOff+Nout) -> T[n][K], bf16 hi/lo
__global__ void tsplit_kernel(const float* __restrict__ W,
                              __nv_bfloat16* __restrict__ Th,
                              __nv_bfloat16* __restrict__ Tl,
                              int K, int ld, int colOff) {
    __shared__ float t[32][33];
    int k0 = blockIdx.y * 32, n0 = blockIdx.x * 32;
    int tx = threadIdx.x, ty = threadIdx.y;
    #pragma unroll
    for (int i = 0; i < 4; i++)
        t[ty + 8*i][tx] = W[(size_t)(k0 + ty + 8*i) * ld + colOff + n0 + tx];
    __syncthreads();
    #pragma unroll
    for (int i = 0; i < 4; i++) {
        float x = t[tx][ty + 8*i];
        __nv_bfloat16 h = __float2bfloat16_rn(x);
        __nv_bfloat16 l = __float2bfloat16_rn(x - __bfloat162float(h));
        size_t o = (size_t)(n0 + ty + 8*i) * K + k0 + tx;
        Th[o] = h; Tl[o] = l;
    }
}

// W[k][ld] cols [colOff, colOff+Nout) -> T[n][K], single fp16
__global__ void ttrans_kernel(const float* __restrict__ W,
                              __half* __restrict__ Th,
                              int K, int ld, int colOff) {
    __shared__ float t[32][33];
    int k0 = blockIdx.y * 32, n0 = blockIdx.x * 32;
    int tx = threadIdx.x, ty = threadIdx.y;
    #pragma unroll
    for (int i = 0; i < 4; i++)
        t[ty + 8*i][tx] = W[(size_t)(k0 + ty + 8*i) * ld + colOff + n0 + tx];
    __syncthreads();
    #pragma unroll
    for (int i = 0; i < 4; i++) {
        size_t o = (size_t)(n0 + ty + 8*i) * K + k0 + tx;
        Th[o] = __float2half_rn(t[tx][ty + 8*i]);
    }
}

// ================= QK GEMM: bf16x3 (amplified path) =================
#define PADK 40
#define TILE_E (128*PADK)
#define QBUF_BYTES (4*TILE_E*2)       // 40960 B per buffer
#define QKV_SMEM (2*QBUF_BYTES)       // 81920 B

__global__ __launch_bounds__(256, 2) void qk_gemm(const float* __restrict__ bias) {
    extern __shared__ __align__(16) char smem[];
    uint32_t sb = smem_u32(smem);
    int tid = threadIdx.x, wid = tid >> 5, lane = tid & 31;
    int wm = wid & 3, wn = wid >> 2;
    int row0 = blockIdx.y * 128, col0 = blockIdx.x * 128;
    int gid = lane >> 2, tig = lane & 3;

    const __nv_bfloat16* srcs[4] = {gXhi, gXlo, gWqh, gWql};

    float acc[2][8][4];
    #pragma unroll
    for (int i = 0; i < 2; i++)
        #pragma unroll
        for (int j = 0; j < 8; j++)
            #pragma unroll
            for (int q = 0; q < 4; q++) acc[i][j][q] = 0.f;

    auto fill = [&](int s, int c) {
        int k0 = c * 32;
        uint32_t sbase = sb + s * QBUF_BYTES;
        #pragma unroll
        for (int t = 0; t < 4; t++) {
            const __nv_bfloat16* src = srcs[t];
            int rbase = (t < 2) ? row0 : col0;
            #pragma unroll
            for (int j = 0; j < 2; j++) {
                int e = j * 256 + tid;
                int r = e >> 2, v = e & 3;
                uint32_t daddr = sbase + (uint32_t)(t * TILE_E + r * PADK + v * 8) * 2;
                CP16(daddr, src + (size_t)(rbase + r) * DD + k0 + v * 8);
            }
        }
        CP_COMMIT();
    };

    fill(0, 0);
    for (int c = 0; c < 24; c++) {
        if (c < 23) fill((c + 1) & 1, c + 1);
        if (c < 23) CP_WAIT1(); else CP_WAIT0();
        __syncthreads();

        uint32_t base = sb + (c & 1) * QBUF_BYTES;
        uint32_t Ahb = base, Alb = base + TILE_E*2;
        uint32_t Bhb = base + 2*TILE_E*2, Blb = Bhb + TILE_E*2;

        #pragma unroll
        for (int ks = 0; ks < 2; ks++) {
            int kcol = ks * 16 + tig * 2;
            uint32_t ah[2][4], al[2][4];
            #pragma unroll
            for (int mt = 0; mt < 2; mt++) {
                int r = wm * 32 + mt * 16 + gid;
                uint32_t o = (uint32_t)(r * PADK + kcol) * 2;
                ah[mt][0] = lds32(Ahb + o);
                ah[mt][1] = lds32(Ahb + o + 8*PADK*2);
                ah[mt][2] = lds32(Ahb + o + 16);
                ah[mt][3] = lds32(Ahb + o + 8*PADK*2 + 16);
                al[mt][0] = lds32(Alb + o);
                al[mt][1] = lds32(Alb + o + 8*PADK*2);
                al[mt][2] = lds32(Alb + o + 16);
                al[mt][3] = lds32(Alb + o + 8*PADK*2 + 16);
            }
            #pragma unroll
            for (int half = 0; half < 2; half++) {
                uint32_t bh[4][2], bl[4][2];
                #pragma unroll
                for (int nt = 0; nt < 4; nt++) {
                    int n = wn * 64 + half * 32 + nt * 8 + gid;
                    uint32_t o = (uint32_t)(n * PADK + kcol) * 2;
                    bh[nt][0] = lds32(Bhb + o);
                    bh[nt][1] = lds32(Bhb + o + 16);
                    bl[nt][0] = lds32(Blb + o);
                    bl[nt][1] = lds32(Blb + o + 16);
                }
                #pragma unroll
                for (int mt = 0; mt < 2; mt++)
                    #pragma unroll
                    for (int nt = 0; nt < 4; nt++)
                        mma_bf(acc[mt][half*4 + nt], ah[mt], bh[nt]);
                #pragma unroll
                for (int mt = 0; mt < 2; mt++)
                    #pragma unroll
                    for (int nt = 0; nt < 4; nt++)
                        mma_bf(acc[mt][half*4 + nt], ah[mt], bl[nt]);
                #pragma unroll
                for (int mt = 0; mt < 2; mt++)
                    #pragma unroll
                    for (int nt = 0; nt < 4; nt++)
                        mma_bf(acc[mt][half*4 + nt], al[mt], bh[nt]);
            }
        }
        __syncthreads();
    }

    // ---- epilogue: Q,K bf16 hi/lo ----
    #pragma unroll
    for (int mt = 0; mt < 2; mt++) {
        int m_lo = row0 + wm * 32 + mt * 16 + gid;
        int m_hi = m_lo + 8;
        #pragma unroll
        for (int j = 0; j < 8; j++) {
            int nc = col0 + wn * 64 + (j >> 2) * 32 + (j & 3) * 8 + tig * 2;
            float b0 = bias[nc], b1 = bias[nc + 1];
            float* cc = acc[mt][j];
            float v0 = cc[0] + b0, v1 = cc[1] + b1;
            float v2 = cc[2] + b0, v3 = cc[3] + b1;
            int which = (nc >= DD) ? 1 : 0;
            int rem = nc - which * DD;
            int h = rem >> 6, hs = rem & 63;
            int p0 = m_lo >> 10, n0 = m_lo & 1023;
            int p1 = m_hi >> 10, n1 = m_hi & 1023;
            int ph0 = p0 * HH + h, ph1 = p1 * HH + h;
            __nv_bfloat16* dh = which ? gKh : gQh;
            __nv_bfloat16* dl = which ? gKl : gQl;
            size_t o0 = (((size_t)ph0 << 10) + n0) * HSZ + hs;
            size_t o1 = (((size_t)ph1 << 10) + n1) * HSZ + hs;
            uint32_t whi, wlo;
            split2(v0, v1, whi, wlo);
            *(uint32_t*)&dh[o0] = whi; *(uint32_t*)&dl[o0] = wlo;
            split2(v2, v3, whi, wlo);
            *(uint32_t*)&dh[o1] = whi; *(uint32_t*)&dl[o1] = wlo;
        }
    }
}

// ================= V GEMM: fp16 1-term (linear path) =================
#define PBUF_BYTES (2*TILE_E*2)       // 20480 B per buffer
#define PROJ_SMEM (2*PBUF_BYTES)      // 40960 B

__global__ __launch_bounds__(256, 2) void v_gemm(const float* __restrict__ bias) {
    extern __shared__ __align__(16) char smem[];
    uint32_t sb = smem_u32(smem);
    int tid = threadIdx.x, wid = tid >> 5, lane = tid & 31;
    int wm = wid & 3, wn = wid >> 2;
    int row0 = blockIdx.y * 128, col0 = blockIdx.x * 128;
    int gid = lane >> 2, tig = lane & 3;

    const __half* srcs[2] = {gXf, gWv};

    float acc[2][8][4];
    #pragma unroll
    for (int i = 0; i < 2; i++)
        #pragma unroll
        for (int j = 0; j < 8; j++)
            #pragma unroll
            for (int q = 0; q < 4; q++) acc[i][j][q] = 0.f;

    auto fill = [&](int s, int c) {
        int k0 = c * 32;
        uint32_t sbase = sb + s * PBUF_BYTES;
        #pragma unroll
        for (int t = 0; t < 2; t++) {
            const __half* src = srcs[t];
            int rbase = (t < 1) ? row0 : col0;
            #pragma unroll
            for (int j = 0; j < 2; j++) {
                int e = j * 256 + tid;
                int r = e >> 2, v = e & 3;
                uint32_t daddr = sbase + (uint32_t)(t * TILE_E + r * PADK + v * 8) * 2;
                CP16(daddr, src + (size_t)(rbase + r) * DD + k0 + v * 8);
            }
        }
        CP_COMMIT();
    };

    fill(0, 0);
    for (int c = 0; c < 24; c++) {
        if (c < 23) fill((c + 1) & 1, c + 1);
        if (c < 23) CP_WAIT1(); else CP_WAIT0();
        __syncthreads();

        uint32_t base = sb + (c & 1) * PBUF_BYTES;
        uint32_t Ab = base, Bb = base + TILE_E*2;

        #pragma unroll
        for (int ks = 0; ks < 2; ks++) {
            int kcol = ks * 16 + tig * 2;
            uint32_t aa[2][4];
            #pragma unroll
            for (int mt = 0; mt < 2; mt++) {
                int r = wm * 32 + mt * 16 + gid;
                uint32_t o = (uint32_t)(r * PADK + kcol) * 2;
                aa[mt][0] = lds32(Ab + o);
                aa[mt][1] = lds32(Ab + o + 8*PADK*2);
                aa[mt][2] = lds32(Ab + o + 16);
                aa[mt][3] = lds32(Ab + o + 8*PADK*2 + 16);
            }
            #pragma unroll
            for (int half = 0; half < 2; half++) {
                uint32_t bb[4][2];
                #pragma unroll
                for (int nt = 0; nt < 4; nt++) {
                    int n = wn * 64 + half * 32 + nt * 8 + gid;
                    uint32_t o = (uint32_t)(n * PADK + kcol) * 2;
                    bb[nt][0] = lds32(Bb + o);
                    bb[nt][1] = lds32(Bb + o + 16);
                }
                #pragma unroll
                for (int mt = 0; mt < 2; mt++)
                    #pragma unroll
                    for (int nt = 0; nt < 4; nt++)
                        mma_hf(acc[mt][half*4 + nt], aa[mt], bb[nt]);
            }
        }
        __syncthreads();
    }

    // ---- epilogue: scatter into gVt [ph][hs][n] fp16 ----
    #pragma unroll
    for (int mt = 0; mt < 2; mt++) {
        int m_lo = row0 + wm * 32 + mt * 16 + gid;
        int m_hi = m_lo + 8;
        #pragma unroll
        for (int j = 0; j < 8; j++) {
            int nc = col0 + wn * 64 + (j >> 2) * 32 + (j & 3) * 8 + tig * 2;
            float b0 = bias[nc], b1 = bias[nc + 1];
            float* cc = acc[mt][j];
            float v0 = cc[0] + b0, v1 = cc[1] + b1;
            float v2 = cc[2] + b0, v3 = cc[3] + b1;
            int h = nc >> 6, hs = nc & 63;
            int p0 = m_lo >> 10, n0 = m_lo & 1023;
            int p1 = m_hi >> 10, n1 = m_hi & 1023;
            size_t r0 = ((size_t)(p0 * HH + h) * HSZ + hs) * NN;
            size_t r1 = ((size_t)(p1 * HH + h) * HSZ + hs) * NN;
            gVt[r0 + n0]      = __float2half_rn(v0);
            gVt[r0 + NN + n0] = __float2half_rn(v1);
            gVt[r1 + n1]      = __float2half_rn(v2);
            gVt[r1 + NN + n1] = __float2half_rn(v3);
        }
    }
}

// ================= proj GEMM: fp16 1-term =================
__global__ __launch_bounds__(256, 2) void proj_gemm(const float* __restrict__ bias,
                                                    float* __restrict__ out) {
    extern __shared__ __align__(16) char smem[];
    uint32_t sb = smem_u32(smem);
    int tid = threadIdx.x, wid = tid >> 5, lane = tid & 31;
    int wm = wid & 3, wn = wid >> 2;
    int row0 = blockIdx.y * 128, col0 = blockIdx.x * 128;
    int gid = lane >> 2, tig = lane & 3;

    const __half* srcs[2] = {gCt, gWp};

    float acc[2][8][4];
    #pragma unroll
    for (int i = 0; i < 2; i++)
        #pragma unroll
        for (int j = 0; j < 8; j++)
            #pragma unroll
            for (int q = 0; q < 4; q++) acc[i][j][q] = 0.f;

    auto fill = [&](int s, int c) {
        int k0 = c * 32;
        uint32_t sbase = sb + s * PBUF_BYTES;
        #pragma unroll
        for (int t = 0; t < 2; t++) {
            const __half* src = srcs[t];
            int rbase = (t < 1) ? row0 : col0;
            #pragma unroll
            for (int j = 0; j < 2; j++) {
                int e = j * 256 + tid;
                int r = e >> 2, v = e & 3;
                uint32_t daddr = sbase + (uint32_t)(t * TILE_E + r * PADK + v * 8) * 2;
                CP16(daddr, src + (size_t)(rbase + r) * DD + k0 + v * 8);
            }
        }
        CP_COMMIT();
    };

    fill(0, 0);
    for (int c = 0; c < 24; c++) {
        if (c < 23) fill((c + 1) & 1, c + 1);
        if (c < 23) CP_WAIT1(); else CP_WAIT0();
        __syncthreads();

        uint32_t base = sb + (c & 1) * PBUF_BYTES;
        uint32_t Ab = base, Bb = base + TILE_E*2;

        #pragma unroll
        for (int ks = 0; ks < 2; ks++) {
            int kcol = ks * 16 + tig * 2;
            uint32_t aa[2][4];
            #pragma unroll
            for (int mt = 0; mt < 2; mt++) {
                int r = wm * 32 + mt * 16 + gid;
                uint32_t o = (uint32_t)(r * PADK + kcol) * 2;
                aa[mt][0] = lds32(Ab + o);
                aa[mt][1] = lds32(Ab + o + 8*PADK*2);
                aa[mt][2] = lds32(Ab + o + 16);
                aa[mt][3] = lds32(Ab + o + 8*PADK*2 + 16);
            }
            #pragma unroll
            for (int half = 0; half < 2; half++) {
                uint32_t bb[4][2];
                #pragma unroll
                for (int nt = 0; nt < 4; nt++) {
                    int n = wn * 64 + half * 32 + nt * 8 + gid;
                    uint32_t o = (uint32_t)(n * PADK + kcol) * 2;
                    bb[nt][0] = lds32(Bb + o);
                    bb[nt][1] = lds32(Bb + o + 16);
                }
                #pragma unroll
                for (int mt = 0; mt < 2; mt++)
                    #pragma unroll
                    for (int nt = 0; nt < 4; nt++)
                        mma_hf(acc[mt][half*4 + nt], aa[mt], bb[nt]);
            }
        }
        __syncthreads();
    }

    #pragma unroll
    for (int mt = 0; mt < 2; mt++) {
        int m_lo = row0 + wm * 32 + mt * 16 + gid;
        int m_hi = m_lo + 8;
        #pragma unroll
        for (int j = 0; j < 8; j++) {
            int nc = col0 + wn * 64 + (j >> 2) * 32 + (j & 3) * 8 + tig * 2;
            float b0 = bias[nc], b1 = bias[nc + 1];
            float* cc = acc[mt][j];
            *(float2*)&out[(size_t)m_lo * DD + nc] = make_float2(cc[0] + b0, cc[1] + b1);
            *(float2*)&out[(size_t)m_hi * DD + nc] = make_float2(cc[2] + b0, cc[3] + b1);
        }
    }
}

// ================= post-softmax mask term =================
__global__ void maskv_kernel(const float* __restrict__ mask) {
    int ph = blockIdx.x;
    int p = ph / HH;
    int w = threadIdx.x >> 5, lane = threadIdx.x & 31;
    const float* mp = mask + (size_t)p * NN;
    #pragma unroll
    for (int i = 0; i < 8; i++) {
        int hs = w * 8 + i;
        const __half* vh = gVt + ((size_t)ph * HSZ + hs) * NN;
        float acc = 0.f;
        for (int k = lane; k < NN; k += 32)
            acc += mp[k] * __half2float(vh[k]);
        #pragma unroll
        for (int s = 16; s > 0; s >>= 1) acc += __shfl_xor_sync(0xffffffffu, acc, s);
        if (lane == 0) gMV[ph * HSZ + hs] = acc;
    }
}

// ================= flash attention: S bf16x3, PV fp16x1 =================
#define AKS 72
#define KTILE_B (64*AKS*2)          // 9216 B
#define ABUF_B (3*KTILE_B)          // 27648 B
#define ATTN_SMEM (2*ABUF_B)        // 55296 B

__global__ __launch_bounds__(256, 2) void attn_mma() {
    extern __shared__ __align__(16) char smem[];
    uint32_t sb = smem_u32(smem);
    int tid = threadIdx.x, wid = tid >> 5, lane = tid & 31;
    int gid = lane >> 2, tig = lane & 3;
    int qb = blockIdx.x, h = blockIdx.y, p = blockIdx.z;
    int ph = p * HH + h;
    int q0 = qb * 128 + wid * 16;

    uint32_t qh[4][4], ql[4][4];
    {
        const __nv_bfloat16* base_h = gQh + ((size_t)ph * NN + q0) * HSZ;
        const __nv_bfloat16* base_l = gQl + ((size_t)ph * NN + q0) * HSZ;
        #pragma unroll
        for (int kk = 0; kk < 4; kk++) {
            int c = kk * 16 + tig * 2;
            qh[kk][0] = *(const uint32_t*)(base_h + (size_t)gid * HSZ + c);
            qh[kk][1] = *(const uint32_t*)(base_h + (size_t)(gid+8) * HSZ + c);
            qh[kk][2] = *(const uint32_t*)(base_h + (size_t)gid * HSZ + c + 8);
            qh[kk][3] = *(const uint32_t*)(base_h + (size_t)(gid+8) * HSZ + c + 8);
            ql[kk][0] = *(const uint32_t*)(base_l + (size_t)gid * HSZ + c);
            ql[kk][1] = *(const uint32_t*)(base_l + (size_t)(gid+8) * HSZ + c);
            ql[kk][2] = *(const uint32_t*)(base_l + (size_t)gid * HSZ + c + 8);
            ql[kk][3] = *(const uint32_t*)(base_l + (size_t)(gid+8) * HSZ + c + 8);
        }
    }

    float oacc[8][4];
    #pragma unroll
    for (int i = 0; i < 8; i++)
        #pragma unroll
        for (int j = 0; j < 4; j++) oacc[i][j] = 0.f;
    float m0 = -1e30f, m1 = -1e30f, l0 = 0.f, l1 = 0.f;

    const __nv_bfloat16* Kh_g = gKh + (size_t)ph * NN * HSZ;
    const __nv_bfloat16* Kl_g = gKl + (size_t)ph * NN * HSZ;
    const __half* V_g = gVt + (size_t)ph * HSZ * NN;

    auto fill = [&](int s, int kb) {
        uint32_t base = sb + s * ABUF_B;
        #pragma unroll
        for (int j = 0; j < 2; j++) {
            int e = j * 256 + tid;
            int r = e >> 3, ch = e & 7;
            uint32_t d = base + (uint32_t)(r * AKS + ch * 8) * 2;
            CP16(d, Kh_g + (size_t)(kb*64 + r) * HSZ + ch * 8);
            CP16(d + KTILE_B, Kl_g + (size_t)(kb*64 + r) * HSZ + ch * 8);
        }
        #pragma unroll
        for (int j = 0; j < 2; j++) {
            int e = j * 256 + tid;
            int r = e >> 3, ch = e & 7;
            uint32_t d = base + 2*KTILE_B + (uint32_t)(r * AKS + ch * 8) * 2;
            CP16(d, V_g + (size_t)r * NN + kb*64 + ch * 8);
        }
        CP_COMMIT();
    };

    fill(0, 0);
    for (int kb = 0; kb < 16; kb++) {
        if (kb < 15) fill((kb + 1) & 1, kb + 1);
        if (kb < 15) CP_WAIT1(); else CP_WAIT0();
        __syncthreads();

        uint32_t base = sb + (kb & 1) * ABUF_B;
        uint32_t Khb = base, Klb = base + KTILE_B, Vb = base + 2*KTILE_B;

        float sacc[8][4];
        #pragma unroll
        for (int nt = 0; nt < 8; nt++)
            #pragma unroll
            for (int j = 0; j < 4; j++) sacc[nt][j] = 0.f;
        #pragma unroll
        for (int kk = 0; kk < 4; kk++) {
            uint32_t co = (uint32_t)(kk*16 + tig*2) * 2;
            #pragma unroll
            for (int g = 0; g < 2; g++) {
                uint32_t bh[4][2], bl[4][2];
                #pragma unroll
                for (int n4 = 0; n4 < 4; n4++) {
                    uint32_t ro = (uint32_t)(((g*4 + n4)*8 + gid) * AKS) * 2;
                    bh[n4][0] = lds32(Khb + ro + co);
                    bh[n4][1] = lds32(Khb + ro + co + 16);
                    bl[n4][0] = lds32(Klb + ro + co);
                    bl[n4][1] = lds32(Klb + ro + co + 16);
                }
                #pragma unroll
                for (int n4 = 0; n4 < 4; n4++) mma_bf(sacc[g*4+n4], qh[kk], bh[n4]);
                #pragma unroll
                for (int n4 = 0; n4 < 4; n4++) mma_bf(sacc[g*4+n4], qh[kk], bl[n4]);
                #pragma unroll
                for (int n4 = 0; n4 < 4; n4++) mma_bf(sacc[g*4+n4], ql[kk], bh[n4]);
            }
        }

        float mx0 = -1e30f, mx1 = -1e30f;
        #pragma unroll
        for (int nt = 0; nt < 8; nt++) {
            mx0 = fmaxf(mx0, fmaxf(sacc[nt][0], sacc[nt][1]));
            mx1 = fmaxf(mx1, fmaxf(sacc[nt][2], sacc[nt][3]));
        }
        mx0 = fmaxf(mx0, __shfl_xor_sync(0xffffffffu, mx0, 1));
        mx0 = fmaxf(mx0, __shfl_xor_sync(0xffffffffu, mx0, 2));
        mx1 = fmaxf(mx1, __shfl_xor_sync(0xffffffffu, mx1, 1));
        mx1 = fmaxf(mx1, __shfl_xor_sync(0xffffffffu, mx1, 2));
        float nm0 = fmaxf(m0, mx0), nm1 = fmaxf(m1, mx1);
        float corr0 = exp2f((m0 - nm0) * SCLOG2);
        float corr1 = exp2f((m1 - nm1) * SCLOG2);
        m0 = nm0; m1 = nm1;
        float rs0 = 0.f, rs1 = 0.f;
        #pragma unroll
        for (int nt = 0; nt < 8; nt++) {
            sacc[nt][0] = exp2f((sacc[nt][0] - nm0) * SCLOG2);
            sacc[nt][1] = exp2f((sacc[nt][1] - nm0) * SCLOG2);
            sacc[nt][2] = exp2f((sacc[nt][2] - nm1) * SCLOG2);
            sacc[nt][3] = exp2f((sacc[nt][3] - nm1) * SCLOG2);
            rs0 += sacc[nt][0] + sacc[nt][1];
            rs1 += sacc[nt][2] + sacc[nt][3];
        }
        rs0 += __shfl_xor_sync(0xffffffffu, rs0, 1);
        rs0 += __shfl_xor_sync(0xffffffffu, rs0, 2);
        rs1 += __shfl_xor_sync(0xffffffffu, rs1, 1);
        rs1 += __shfl_xor_sync(0xffffffffu, rs1, 2);
        l0 = l0 * corr0 + rs0;
        l1 = l1 * corr1 + rs1;
        #pragma unroll
        for (int nt = 0; nt < 8; nt++) {
            oacc[nt][0] *= corr0; oacc[nt][1] *= corr0;
            oacc[nt][2] *= corr1; oacc[nt][3] *= corr1;
        }

        #pragma unroll
        for (int kblk = 0; kblk < 4; kblk++) {
            uint32_t ap[4];
            ap[0] = pack2h(sacc[2*kblk][0],   sacc[2*kblk][1]);
            ap[1] = pack2h(sacc[2*kblk][2],   sacc[2*kblk][3]);
            ap[2] = pack2h(sacc[2*kblk+1][0], sacc[2*kblk+1][1]);
            ap[3] = pack2h(sacc[2*kblk+1][2], sacc[2*kblk+1][3]);
            uint32_t co = (uint32_t)(kblk*16 + tig*2) * 2;
            #pragma unroll
            for (int g = 0; g < 2; g++) {
                uint32_t bb[4][2];
                #pragma unroll
                for (int n4 = 0; n4 < 4; n4++) {
                    uint32_t ro = (uint32_t)(((g*4 + n4)*8 + gid) * AKS) * 2;
                    bb[n4][0] = lds32(Vb + ro + co);
                    bb[n4][1] = lds32(Vb + ro + co + 16);
                }
                #pragma unroll
                for (int n4 = 0; n4 < 4; n4++) mma_hf(oacc[g*4+n4], ap, bb[n4]);
            }
        }
        __syncthreads();
    }

    float inv0 = 1.0f / l0, inv1 = 1.0f / l1;
    int q_lo = q0 + gid;
    int q_hi = q_lo + 8;
    #pragma unroll
    for (int nt = 0; nt < 8; nt++) {
        int hs = nt*8 + tig*2;
        float mv0 = gMV[ph*HSZ + hs], mv1 = gMV[ph*HSZ + hs + 1];
        float v0 = oacc[nt][0]*inv0 + mv0, v1 = oacc[nt][1]*inv0 + mv1;
        float v2 = oacc[nt][2]*inv1 + mv0, v3 = oacc[nt][3]*inv1 + mv1;
        size_t o0 = ((size_t)p*NN + q_lo) * DD + h*HSZ + hs;
        size_t o1 = ((size_t)p*NN + q_hi) * DD + h*HSZ + hs;
        *(uint32_t*)&gCt[o0] = pack2h(v0, v1);
        *(uint32_t*)&gCt[o1] = pack2h(v2, v3);
    }
}

extern "C" void kernel_launch(void* const* d_in, const int* in_sizes, int n_in,
                              void* d_out, int out_size) {
    const float* X      = (const float*)d_in[0];
    const float* mask   = (const float*)d_in[1];
    const float* qkv_w  = (const float*)d_in[2];
    const float* qkv_b  = (const float*)d_in[3];
    const float* proj_w = (const float*)d_in[4];
    const float* proj_b = (const float*)d_in[5];
    float* out = (float*)d_out;

    cudaFuncSetAttribute(qk_gemm, cudaFuncAttributeMaxDynamicSharedMemorySize, QKV_SMEM);
    cudaFuncSetAttribute(v_gemm, cudaFuncAttributeMaxDynamicSharedMemorySize, PROJ_SMEM);
    cudaFuncSetAttribute(proj_gemm, cudaFuncAttributeMaxDynamicSharedMemorySize, PROJ_SMEM);
    cudaFuncSetAttribute(attn_mma, cudaFuncAttributeMaxDynamicSharedMemorySize, ATTN_SMEM);

    __nv_bfloat16 *xhi, *xlo, *wqh, *wql;
    __half *xf, *wv, *wp;
    cudaGetSymbolAddress((void**)&xhi, gXhi);
    cudaGetSymbolAddress((void**)&xlo, gXlo);
    cudaGetSymbolAddress((void**)&xf, gXf);
    cudaGetSymbolAddress((void**)&wqh, gWqh);
    cudaGetSymbolAddress((void**)&wql, gWql);
    cudaGetSymbolAddress((void**)&wv, gWv);
    cudaGetSymbolAddress((void**)&wp, gWp);

    split_kernel<<<(PP*NN*DD/4 + 255)/256, 256>>>(X, xhi, xlo, xf, PP*NN*DD/4);
    tsplit_kernel<<<dim3(2*DD/32, DD/32), dim3(32,8)>>>(qkv_w, wqh, wql, DD, 3*DD, 0);
    ttrans_kernel<<<dim3(DD/32, DD/32), dim3(32,8)>>>(qkv_w, wv, DD, 3*DD, 2*DD);
    ttrans_kernel<<<dim3(DD/32, DD/32), dim3(32,8)>>>(proj_w, wp, DD, DD, 0);
    qk_gemm<<<dim3(2*DD/128, PP*NN/128), 256, QKV_SMEM>>>(qkv_b);
    v_gemm<<<dim3(DD/128, PP*NN/128), 256, PROJ_SMEM>>>(qkv_b + 2*DD);
    maskv_kernel<<<PP*HH, 256>>>(mask);
    attn_mma<<<dim3(NN/128, HH, PP), 256, ATTN_SMEM>>>();
    proj_gemm<<<dim3(DD/128, PP*NN/128), 256, PROJ_SMEM>>>(proj_b, out);
}